// round 11
// baseline (speedup 1.0000x reference)
#include <cuda_runtime.h>
#include <cuda_bf16.h>
#include <cstdint>
#include <cstddef>

#define BSZ   40
#define TSZ   20
#define FEAD  200
#define HDIM  1024
#define OUTD  1095
#define LNUM  12
#define MROWS (BSZ * TSZ)          // 800
#define MPAD  896                  // 7 * 128
#define OUT_ELEMS (MROWS * OUTD)   // 876000

// ---------------------------------------------------------------------------
// Scratch
// ---------------------------------------------------------------------------
__device__ __align__(16) float g_h [MROWS * HDIM];
__device__ __align__(16) float g_U [MROWS * 3 * HDIM];
__device__ __align__(16) __nv_bfloat16 g_xthi[MROWS * FEAD];
__device__ __align__(16) __nv_bfloat16 g_xtlo[MROWS * FEAD];
__device__ __align__(16) __nv_bfloat16 g_Ahi [MPAD * HDIM];
__device__ __align__(16) __nv_bfloat16 g_Alo [MPAD * HDIM];
__device__ __align__(16) __nv_bfloat16 g_A2hi[MROWS * HDIM];
__device__ __align__(16) __nv_bfloat16 g_A2lo[MROWS * HDIM];

// ---------------------------------------------------------------------------
// PTX helpers
// ---------------------------------------------------------------------------
__device__ __forceinline__ void cpa16(void* dst, const void* src, bool pred) {
    unsigned d = (unsigned)__cvta_generic_to_shared(dst);
    if (pred) {
        asm volatile("cp.async.cg.shared.global [%0], [%1], 16;\n" :: "r"(d), "l"(src) : "memory");
    } else {
        uint4 z = {0u, 0u, 0u, 0u};
        *reinterpret_cast<uint4*>(dst) = z;
    }
}
__device__ __forceinline__ void cpa16s(uint32_t daddr, const void* src) {
    asm volatile("cp.async.cg.shared.global [%0], [%1], 16;\n" :: "r"(daddr), "l"(src) : "memory");
}
__device__ __forceinline__ void cp_commit() { asm volatile("cp.async.commit_group;\n" ::: "memory"); }
__device__ __forceinline__ void cp_wait1()  { asm volatile("cp.async.wait_group 1;\n" ::: "memory"); }
__device__ __forceinline__ void cp_wait0()  { asm volatile("cp.async.wait_group 0;\n" ::: "memory"); }

__device__ __forceinline__ void sts64(uint32_t addr, uint32_t a, uint32_t b) {
    asm volatile("st.shared.v2.u32 [%0], {%1,%2};\n" :: "r"(addr), "r"(a), "r"(b) : "memory");
}
__device__ __forceinline__ void ldsm_x4(uint32_t* r, uint32_t a) {
    asm volatile("ldmatrix.sync.aligned.m8n8.x4.shared.b16 {%0,%1,%2,%3}, [%4];\n"
                 : "=r"(r[0]), "=r"(r[1]), "=r"(r[2]), "=r"(r[3]) : "r"(a));
}
__device__ __forceinline__ void ldsm_x4_p(uint32_t* r, const void* p) {
    unsigned a = (unsigned)__cvta_generic_to_shared(p);
    ldsm_x4(r, a);
}
__device__ __forceinline__ void ldsm_x4_t(uint32_t* r, uint32_t a) {
    asm volatile("ldmatrix.sync.aligned.m8n8.x4.trans.shared.b16 {%0,%1,%2,%3}, [%4];\n"
                 : "=r"(r[0]), "=r"(r[1]), "=r"(r[2]), "=r"(r[3]) : "r"(a));
}
__device__ __forceinline__ void ldsm_x2_t(uint32_t* r, const void* p) {
    unsigned a = (unsigned)__cvta_generic_to_shared(p);
    asm volatile("ldmatrix.sync.aligned.m8n8.x2.trans.shared.b16 {%0,%1}, [%2];\n"
                 : "=r"(r[0]), "=r"(r[1]) : "r"(a));
}
__device__ __forceinline__ void mma_bf16(float& d0, float& d1, float& d2, float& d3,
                                         const uint32_t a[4], const uint32_t b[2]) {
    asm volatile("mma.sync.aligned.m16n8k16.row.col.f32.bf16.bf16.f32 "
                 "{%0,%1,%2,%3}, {%4,%5,%6,%7}, {%8,%9}, {%0,%1,%2,%3};\n"
                 : "+f"(d0), "+f"(d1), "+f"(d2), "+f"(d3)
                 : "r"(a[0]), "r"(a[1]), "r"(a[2]), "r"(a[3]), "r"(b[0]), "r"(b[1]));
}
__device__ __forceinline__ float tanh_fast(float x) {
    float y; asm("tanh.approx.f32 %0, %1;" : "=f"(y) : "f"(x)); return y;
}
__device__ __forceinline__ float sigmoid_fast(float x) {
    return 1.0f / (1.0f + __expf(-x));
}
__device__ __forceinline__ uint32_t pack2bf(float a, float b) {
    __nv_bfloat162 v(__float2bfloat16(a), __float2bfloat16(b));
    return *reinterpret_cast<uint32_t*>(&v);
}
// split two fp32 into packed hi-pair and lo-pair bf16x2
__device__ __forceinline__ void split2(float a, float b, uint32_t& h, uint32_t& l) {
    __nv_bfloat16 ha = __float2bfloat16(a), hb = __float2bfloat16(b);
    float la = a - __bfloat162float(ha);
    float lb = b - __bfloat162float(hb);
    __nv_bfloat162 H(ha, hb), L(__float2bfloat16(la), __float2bfloat16(lb));
    h = *reinterpret_cast<uint32_t*>(&H);
    l = *reinterpret_cast<uint32_t*>(&L);
}

// ---------------------------------------------------------------------------
// Preprocessing
// ---------------------------------------------------------------------------
__global__ void transpose_split_kernel(const float* __restrict__ x,
                                       __nv_bfloat16* __restrict__ hi,
                                       __nv_bfloat16* __restrict__ lo) {
    int idx = blockIdx.x * blockDim.x + threadIdx.x;
    if (idx >= MROWS * FEAD) return;
    int f = idx % FEAD;
    int m = idx / FEAD;
    int b = m % BSZ;
    int t = m / BSZ;
    float v = x[((size_t)b * TSZ + t) * FEAD + f];
    __nv_bfloat16 h = __float2bfloat16(v);
    hi[idx] = h;
    lo[idx] = __float2bfloat16(v - __bfloat162float(h));
}

__global__ void zeropad_kernel(__nv_bfloat16* __restrict__ hi, __nv_bfloat16* __restrict__ lo) {
    int i = blockIdx.x * blockDim.x + threadIdx.x;
    int n = (MPAD - MROWS) * HDIM / 2;
    if (i >= n) return;
    reinterpret_cast<uint32_t*>(hi + (size_t)MROWS * HDIM)[i] = 0u;
    reinterpret_cast<uint32_t*>(lo + (size_t)MROWS * HDIM)[i] = 0u;
}

// ---------------------------------------------------------------------------
// U-GEMM (mma.sync, bf16x3): U[800,3072] = A[.,1024] @ W[1024,3072]
// B staged directly from fp32 (LDG -> split -> STS); A via cp.async.
// BM=128, BN=192, BK=32, 384 threads (4x3 warps, 32x64 warp tile).
// ---------------------------------------------------------------------------
#define UK   1024
#define UN   3072
#define UBM  128
#define UBN  192
#define UBK  32
#define UNIT (UK / UBK)          // 32
#define UA_PB   (UBM * 40 * 2)   // 10240 B
#define UB_PB   (UBK * 200 * 2)  // 12800 B
#define U_SM_AH 0
#define U_SM_AL (U_SM_AH + 2 * UA_PB)
#define U_SM_BH (U_SM_AL + 2 * UA_PB)
#define U_SM_BL (U_SM_BH + 2 * UB_PB)
#define U_SM_TOTAL (U_SM_BL + 2 * UB_PB)   // 92160

__global__ __launch_bounds__(384, 1)
void u_gemm_kernel(const __nv_bfloat16* __restrict__ Ahi,
                   const __nv_bfloat16* __restrict__ Alo,
                   const float* __restrict__ Bf,
                   float* __restrict__ U) {
    extern __shared__ char dsm[];
    uint32_t smem;
    asm("{ .reg .u64 t; cvta.to.shared.u64 t, %1; cvt.u32.u64 %0, t; }"
        : "=r"(smem) : "l"(dsm));

    const int tid  = threadIdx.x;
    const int warp = tid >> 5;
    const int lane = tid & 31;
    const int wrow = warp / 3;
    const int wcol = warp % 3;
    const int row0 = blockIdx.y * UBM;
    const int col0 = blockIdx.x * UBN;

    float acc[2][4][2][4];
#pragma unroll
    for (int a = 0; a < 2; a++)
#pragma unroll
        for (int b = 0; b < 4; b++)
#pragma unroll
            for (int c = 0; c < 2; c++)
#pragma unroll
                for (int d = 0; d < 4; d++) acc[a][b][c][d] = 0.0f;

    // B chunk mapping: 1536 float4 chunks (32 rows x 48); 4 per thread
    int br[4], bn[4];
#pragma unroll
    for (int i = 0; i < 4; i++) {
        int c = tid + i * 384;
        br[i] = c / 48;
        bn[i] = c % 48;
    }
    float4 breg[4];

    auto ldgB = [&](int it) {
#pragma unroll
        for (int i = 0; i < 4; i++) {
            breg[i] = __ldg(reinterpret_cast<const float4*>(
                Bf + (size_t)(it * UBK + br[i]) * UN + col0 + bn[i] * 4));
        }
    };
    auto stsB = [&](int buf) {
#pragma unroll
        for (int i = 0; i < 4; i++) {
            uint32_t h0, l0, h1, l1;
            split2(breg[i].x, breg[i].y, h0, l0);
            split2(breg[i].z, breg[i].w, h1, l1);
            uint32_t off = (uint32_t)(br[i] * 400 + bn[i] * 8) + buf * UB_PB;
            sts64(smem + U_SM_BH + off, h0, h1);
            sts64(smem + U_SM_BL + off, l0, l1);
        }
    };
    auto stageA = [&](int it, int buf) {
        const int k0 = it * UBK;
#pragma unroll
        for (int i = 0; i < 3; i++) {
            int idx = tid + i * 384;
            if (idx < 1024) {
                int part = idx >> 9;
                int c = idx & 511;
                int r = c >> 2, kc = c & 3;
                uint32_t daddr = smem + (part ? U_SM_AL : U_SM_AH) + buf * UA_PB
                               + r * 80 + kc * 16;
                const __nv_bfloat16* src = part ? Alo : Ahi;
                cpa16s(daddr, src + (size_t)(row0 + r) * UK + k0 + kc * 8);
            }
        }
    };

    // Prologue
    ldgB(0);
    stageA(0, 0);
    cp_commit();
    stsB(0);
    ldgB(1);

    for (int it = 0; it < UNIT; ++it) {
        const int buf = it & 1;
        if (it + 1 < UNIT) {
            stsB(buf ^ 1);                 // B(it+1)
            stageA(it + 1, buf ^ 1);
            cp_commit();
            if (it + 2 < UNIT) ldgB(it + 2);
            cp_wait1();
        } else {
            cp_wait0();
        }
        __syncthreads();

#pragma unroll
        for (int kk = 0; kk < 2; kk++) {
            uint32_t ah[2][4], al[2][4], bh[4][4], bl[4][4];
#pragma unroll
            for (int mt = 0; mt < 2; mt++) {
                uint32_t off = (uint32_t)((wrow * 32 + mt * 16 + (lane & 15)) * 80
                             + (kk * 16 + ((lane >> 4) << 3)) * 2) + buf * UA_PB;
                ldsm_x4(ah[mt], smem + U_SM_AH + off);
                ldsm_x4(al[mt], smem + U_SM_AL + off);
            }
#pragma unroll
            for (int nt = 0; nt < 4; nt++) {
                uint32_t off = (uint32_t)((kk * 16 + (lane & 15)) * 400
                             + (wcol * 64 + nt * 16 + ((lane >> 4) << 3)) * 2) + buf * UB_PB;
                ldsm_x4_t(bh[nt], smem + U_SM_BH + off);
                ldsm_x4_t(bl[nt], smem + U_SM_BL + off);
            }
#pragma unroll
            for (int mt = 0; mt < 2; mt++) {
#pragma unroll
                for (int nt = 0; nt < 4; nt++) {
#pragma unroll
                    for (int h8 = 0; h8 < 2; h8++) {
                        float* d = acc[mt][nt][h8];
                        mma_bf16(d[0], d[1], d[2], d[3], ah[mt], &bh[nt][h8 * 2]);
                        mma_bf16(d[0], d[1], d[2], d[3], ah[mt], &bl[nt][h8 * 2]);
                        mma_bf16(d[0], d[1], d[2], d[3], al[mt], &bh[nt][h8 * 2]);
                    }
                }
            }
        }
        __syncthreads();
    }

#pragma unroll
    for (int mt = 0; mt < 2; mt++) {
#pragma unroll
        for (int half = 0; half < 2; half++) {
            int row = row0 + wrow * 32 + mt * 16 + (lane >> 2) + half * 8;
            if (row >= MROWS) continue;
            float* dst = U + (size_t)row * UN;
#pragma unroll
            for (int nt = 0; nt < 4; nt++) {
#pragma unroll
                for (int h8 = 0; h8 < 2; h8++) {
                    int col = col0 + wcol * 64 + nt * 16 + h8 * 8 + ((lane & 3) << 1);
                    float2 v;
                    v.x = acc[mt][nt][h8][half * 2 + 0];
                    v.y = acc[mt][nt][h8][half * 2 + 1];
                    *reinterpret_cast<float2*>(dst + col) = v;
                }
            }
        }
    }
}

// ---------------------------------------------------------------------------
// Dense GEMM (mma.sync, bf16x3): B staged from fp32 with fused split.
// BM=64, BN=128, BK=16, 256 threads.
// ---------------------------------------------------------------------------
#define BM 64
#define BN 128
#define BK 16

template<int RELU, int REMAP, int WF32, int WSPLIT>
__global__ __launch_bounds__(256, 2)
void mma_gemm(const __nv_bfloat16* __restrict__ Ahi, const __nv_bfloat16* __restrict__ Alo,
              const float* __restrict__ Bf,
              const float* __restrict__ bias,
              float* __restrict__ Cf,
              __nv_bfloat16* __restrict__ Chi, __nv_bfloat16* __restrict__ Clo,
              int M, int K, int N) {
    __shared__ __nv_bfloat16 sAh[2][BM][24];
    __shared__ __nv_bfloat16 sAl[2][BM][24];
    __shared__ __nv_bfloat16 sBh[2][BK][136];
    __shared__ __nv_bfloat16 sBl[2][BK][136];

    const int tid  = threadIdx.x;
    const int lane = tid & 31;
    const int warp = tid >> 5;
    const int wm = warp >> 2;
    const int wn = warp & 3;
    const int row0 = blockIdx.y * BM;
    const int col0 = blockIdx.x * BN;
    const bool n4ok = ((N & 3) == 0);

    const int a_part = tid >> 7;
    const int a_m    = (tid & 127) >> 1;
    const int a_half = tid & 1;

    float acc[2][4][4];
#pragma unroll
    for (int mt = 0; mt < 2; mt++)
#pragma unroll
        for (int nt = 0; nt < 4; nt++)
#pragma unroll
            for (int j = 0; j < 4; j++) acc[mt][nt][j] = 0.0f;

    const int NTILES = (K + BK - 1) / BK;

    // B chunks: 512 float4 (16 rows x 32); 2 per thread
    const int br0 = tid >> 5, bn0 = tid & 31;      // chunk tid
    const int br1 = (tid + 256) >> 5, bn1 = (tid + 256) & 31;
    float breg[2][4];

    auto ldgB = [&](int k0) {
        int rr[2] = {br0, br1};
        int nn[2] = {bn0, bn1};
#pragma unroll
        for (int i = 0; i < 2; i++) {
            int gk = k0 + rr[i];
            int gn = col0 + nn[i] * 4;
            if (n4ok) {
                if (gk < K && gn < N) {
                    float4 v = __ldg(reinterpret_cast<const float4*>(Bf + (size_t)gk * N + gn));
                    breg[i][0] = v.x; breg[i][1] = v.y; breg[i][2] = v.z; breg[i][3] = v.w;
                } else {
                    breg[i][0] = breg[i][1] = breg[i][2] = breg[i][3] = 0.0f;
                }
            } else {
#pragma unroll
                for (int j = 0; j < 4; j++)
                    breg[i][j] = (gk < K && gn + j < N) ? Bf[(size_t)gk * N + gn + j] : 0.0f;
            }
        }
    };
    auto stsB = [&](int buf) {
        int rr[2] = {br0, br1};
        int nn[2] = {bn0, bn1};
#pragma unroll
        for (int i = 0; i < 2; i++) {
            uint32_t h0, l0, h1, l1;
            split2(breg[i][0], breg[i][1], h0, l0);
            split2(breg[i][2], breg[i][3], h1, l1);
            uint32_t ah = (uint32_t)__cvta_generic_to_shared(&sBh[buf][rr[i]][nn[i] * 4]);
            uint32_t al = (uint32_t)__cvta_generic_to_shared(&sBl[buf][rr[i]][nn[i] * 4]);
            sts64(ah, h0, h1);
            sts64(al, l0, l1);
        }
    };
    auto stageA = [&](int k0, int buf) {
        const __nv_bfloat16* src = a_part ? Alo : Ahi;
        __nv_bfloat16* dst = a_part ? &sAl[buf][a_m][a_half * 8]
                                    : &sAh[buf][a_m][a_half * 8];
        int gr = row0 + a_m;
        int gk = k0 + a_half * 8;
        bool p = (gr < M) && (gk < K);
        cpa16(dst, src + (size_t)gr * K + gk, p);
    };

    // Prologue
    ldgB(0);
    stageA(0, 0);
    cp_commit();
    stsB(0);
    ldgB(BK);

    for (int it = 0; it < NTILES; ++it) {
        const int buf = it & 1;
        if (it + 1 < NTILES) {
            stsB(buf ^ 1);
            stageA((it + 1) * BK, buf ^ 1);
            cp_commit();
            if (it + 2 < NTILES) ldgB((it + 2) * BK);
            cp_wait1();
        } else {
            cp_wait0();
        }
        __syncthreads();

        uint32_t ah[2][4], al[2][4], bh[4][2], bl[4][2];
#pragma unroll
        for (int mt = 0; mt < 2; mt++) {
            int r = wm * 32 + mt * 16 + (lane & 15);
            int kk = (lane >> 4) * 8;
            ldsm_x4_p(ah[mt], &sAh[buf][r][kk]);
            ldsm_x4_p(al[mt], &sAl[buf][r][kk]);
        }
#pragma unroll
        for (int nt = 0; nt < 4; nt++) {
            int n0 = wn * 32 + nt * 8;
            int kr = lane & 15;
            ldsm_x2_t(bh[nt], &sBh[buf][kr][n0]);
            ldsm_x2_t(bl[nt], &sBl[buf][kr][n0]);
        }
#pragma unroll
        for (int mt = 0; mt < 2; mt++) {
#pragma unroll
            for (int nt = 0; nt < 4; nt++) {
                float* d = acc[mt][nt];
                mma_bf16(d[0], d[1], d[2], d[3], ah[mt], bh[nt]);
                mma_bf16(d[0], d[1], d[2], d[3], ah[mt], bl[nt]);
                mma_bf16(d[0], d[1], d[2], d[3], al[mt], bh[nt]);
            }
        }
        __syncthreads();
    }

#pragma unroll
    for (int mt = 0; mt < 2; mt++) {
#pragma unroll
        for (int nt = 0; nt < 4; nt++) {
            int rbase = row0 + wm * 32 + mt * 16 + (lane >> 2);
            int cbase = col0 + wn * 32 + nt * 8 + ((lane & 3) << 1);
#pragma unroll
            for (int half = 0; half < 2; half++) {
                int row = rbase + half * 8;
                if (row >= M) continue;
                int orow = row;
                if (REMAP) {
                    int bb = row % BSZ;
                    int tt = row / BSZ;
                    orow = bb * TSZ + tt;
                }
#pragma unroll
                for (int j = 0; j < 2; j++) {
                    int col = cbase + j;
                    if (col >= N) continue;
                    float v = acc[mt][nt][half * 2 + j];
                    if (bias) v += bias[col];
                    if (RELU) v = fmaxf(v, 0.0f);
                    size_t o = (size_t)orow * N + col;
                    if (WF32) Cf[o] = v;
                    if (WSPLIT) {
                        __nv_bfloat16 h = __float2bfloat16(v);
                        Chi[o] = h;
                        Clo[o] = __float2bfloat16(v - __bfloat162float(h));
                    }
                }
            }
        }
    }
}

// ---------------------------------------------------------------------------
// SRU recurrence, float4-vectorized: one thread = 4 h-channels of one batch b.
// ---------------------------------------------------------------------------
__global__ __launch_bounds__(128)
void sru_scan_kernel(const float* __restrict__ U, const float* __restrict__ c0,
                     const float* __restrict__ sb, float* __restrict__ h,
                     __nv_bfloat16* __restrict__ Ahi, __nv_bfloat16* __restrict__ Alo,
                     float* __restrict__ c_out) {
    int idx4 = blockIdx.x * 128 + threadIdx.x;
    if (idx4 >= BSZ * HDIM / 4) return;
    int e0 = idx4 * 4;
    int hh = e0 & (HDIM - 1);
    int b  = e0 >> 10;

    float4 c4  = *reinterpret_cast<const float4*>(c0 + e0);
    float4 bf4 = *reinterpret_cast<const float4*>(sb + hh);
    float4 br4 = *reinterpret_cast<const float4*>(sb + HDIM + hh);
    float* cc = reinterpret_cast<float*>(&c4);
    float* bfv = reinterpret_cast<float*>(&bf4);
    float* brv = reinterpret_cast<float*>(&br4);

#pragma unroll
    for (int t0 = 0; t0 < TSZ; t0 += 4) {
        float4 xf[4], uf[4], ur[4], hv[4];
#pragma unroll
        for (int i = 0; i < 4; i++) {
            int row = (t0 + i) * BSZ + b;
            const float* Ub = U + (size_t)row * (3 * HDIM) + hh;
            xf[i] = *reinterpret_cast<const float4*>(Ub);
            uf[i] = *reinterpret_cast<const float4*>(Ub + HDIM);
            ur[i] = *reinterpret_cast<const float4*>(Ub + 2 * HDIM);
            hv[i] = *reinterpret_cast<const float4*>(h + (size_t)row * HDIM + hh);
        }
#pragma unroll
        for (int i = 0; i < 4; i++) {
            float* xv = reinterpret_cast<float*>(&xf[i]);
            float* ufv = reinterpret_cast<float*>(&uf[i]);
            float* urv = reinterpret_cast<float*>(&ur[i]);
            float* hvv = reinterpret_cast<float*>(&hv[i]);
            float hn[4];
#pragma unroll
            for (int j = 0; j < 4; j++) {
                float f = sigmoid_fast(ufv[j] + bfv[j]);
                float r = sigmoid_fast(urv[j] + brv[j]);
                cc[j] = f * cc[j] + (1.0f - f) * xv[j];
                hn[j] = r * tanh_fast(cc[j]) + (1.0f - r) * hvv[j];
            }
            size_t o = (size_t)((t0 + i) * BSZ + b) * HDIM + hh;
            float4 hw = {hn[0], hn[1], hn[2], hn[3]};
            *reinterpret_cast<float4*>(h + o) = hw;
            uint2 Hp, Lp;
            uint32_t h0, l0, h1, l1;
            split2(hn[0], hn[1], h0, l0);
            split2(hn[2], hn[3], h1, l1);
            Hp.x = h0; Hp.y = h1;
            Lp.x = l0; Lp.y = l1;
            *reinterpret_cast<uint2*>(Ahi + o) = Hp;
            *reinterpret_cast<uint2*>(Alo + o) = Lp;
        }
    }
    *reinterpret_cast<float4*>(c_out + e0) = c4;
}

// ---------------------------------------------------------------------------
extern "C" void kernel_launch(void* const* d_in, const int* in_sizes, int n_in,
                              void* d_out, int out_size) {
    const float* x      = (const float*)d_in[0];
    const float* hidden = (const float*)d_in[1];
    const float* W1     = (const float*)d_in[2];
    const float* b1     = (const float*)d_in[3];
    const float* sru_W  = (const float*)d_in[4];
    const float* sru_b  = (const float*)d_in[5];
    const float* W3     = (const float*)d_in[6];
    const float* b3     = (const float*)d_in[7];
    const float* W4     = (const float*)d_in[8];
    const float* b4     = (const float*)d_in[9];
    float* out = (float*)d_out;

    float *h, *U;
    __nv_bfloat16 *xthi, *xtlo, *Ahi, *Alo, *A2hi, *A2lo;
    cudaGetSymbolAddress((void**)&h,    g_h);
    cudaGetSymbolAddress((void**)&U,    g_U);
    cudaGetSymbolAddress((void**)&xthi, g_xthi);
    cudaGetSymbolAddress((void**)&xtlo, g_xtlo);
    cudaGetSymbolAddress((void**)&Ahi,  g_Ahi);
    cudaGetSymbolAddress((void**)&Alo,  g_Alo);
    cudaGetSymbolAddress((void**)&A2hi, g_A2hi);
    cudaGetSymbolAddress((void**)&A2lo, g_A2lo);

    static bool attr_set = false;
    if (!attr_set) {
        cudaFuncSetAttribute(u_gemm_kernel,
                             cudaFuncAttributeMaxDynamicSharedMemorySize, U_SM_TOTAL);
        attr_set = true;
    }

    // Preprocessing (tiny now — weight splits are fused into GEMM staging)
    transpose_split_kernel<<<(MROWS * FEAD + 255) / 256, 256>>>(x, xthi, xtlo);
    zeropad_kernel<<<((MPAD - MROWS) * HDIM / 2 + 255) / 256, 256>>>(Ahi, Alo);

    const int GY = (MROWS + BM - 1) / BM;

    // Dense layer 1: h = xt @ W1 + b1 (fp32 + bf16 split out)
    {
        dim3 grid((HDIM + BN - 1) / BN, GY);
        mma_gemm<0, 0, 1, 1><<<grid, 256>>>(xthi, xtlo, W1, b1, h, Ahi, Alo,
                                            MROWS, FEAD, HDIM);
    }

    // SRU layers
    for (int l = 0; l < LNUM; l++) {
        dim3 gridU(UN / UBN, MPAD / UBM);   // 16 x 7 = 112 blocks
        u_gemm_kernel<<<gridU, 384, U_SM_TOTAL>>>(Ahi, Alo,
                                                  sru_W + (size_t)l * HDIM * 3 * HDIM, U);
        sru_scan_kernel<<<(BSZ * HDIM / 4 + 127) / 128, 128>>>(
            U, hidden + (size_t)l * BSZ * HDIM, sru_b + (size_t)l * 2 * HDIM,
            h, Ahi, Alo, out + OUT_ELEMS + (size_t)l * BSZ * HDIM);
    }

    // Dense ReLU with row remap
    {
        dim3 grid((HDIM + BN - 1) / BN, GY);
        mma_gemm<1, 1, 0, 1><<<grid, 256>>>(Ahi, Alo, W3, b3, nullptr, A2hi, A2lo,
                                            MROWS, HDIM, HDIM);
    }

    // Output projection
    {
        dim3 grid((OUTD + BN - 1) / BN, GY);
        mma_gemm<0, 0, 1, 0><<<grid, 256>>>(A2hi, A2lo, W4, b4, out, nullptr, nullptr,
                                            MROWS, HDIM, OUTD);
    }
}

// round 13
// speedup vs baseline: 1.4879x; 1.4879x over previous
#include <cuda_runtime.h>
#include <cuda_bf16.h>
#include <cstdint>
#include <cstddef>

#define BSZ   40
#define TSZ   20
#define FEAD  200
#define HDIM  1024
#define OUTD  1095
#define LNUM  12
#define MROWS (BSZ * TSZ)          // 800
#define MPAD  896                  // 7 * 128
#define OUT_ELEMS (MROWS * OUTD)   // 876000

#define OFF_W1  0
#define N_W1    (FEAD * HDIM)
#define OFF_W3  (OFF_W1 + N_W1)
#define N_W3    (HDIM * HDIM)
#define OFF_W4  (OFF_W3 + N_W3)
#define N_W4    (HDIM * OUTD)
#define N_WSM   (OFF_W4 + N_W4)
#define N_SRU   (LNUM * HDIM * 3 * HDIM)

// ---------------------------------------------------------------------------
// Scratch
// ---------------------------------------------------------------------------
__device__ __align__(16) float g_h [MROWS * HDIM];
__device__ __align__(16) float g_U [MROWS * 3 * HDIM];
__device__ __align__(16) __nv_bfloat16 g_xthi[MROWS * FEAD];
__device__ __align__(16) __nv_bfloat16 g_xtlo[MROWS * FEAD];
__device__ __align__(16) __nv_bfloat16 g_Ahi [MPAD * HDIM];
__device__ __align__(16) __nv_bfloat16 g_Alo [MPAD * HDIM];
__device__ __align__(16) __nv_bfloat16 g_A2hi[MROWS * HDIM];
__device__ __align__(16) __nv_bfloat16 g_A2lo[MROWS * HDIM];
__device__ __align__(16) __nv_bfloat16 g_Wsmhi[N_WSM];
__device__ __align__(16) __nv_bfloat16 g_Wsmlo[N_WSM];
__device__ __align__(16) __nv_bfloat16 g_Wshi[N_SRU];
__device__ __align__(16) __nv_bfloat16 g_Wslo[N_SRU];

// ---------------------------------------------------------------------------
// PTX helpers
// ---------------------------------------------------------------------------
__device__ __forceinline__ void cpa16(void* dst, const void* src, bool pred) {
    unsigned d = (unsigned)__cvta_generic_to_shared(dst);
    if (pred) {
        asm volatile("cp.async.cg.shared.global [%0], [%1], 16;\n" :: "r"(d), "l"(src) : "memory");
    } else {
        uint4 z = {0u, 0u, 0u, 0u};
        *reinterpret_cast<uint4*>(dst) = z;
    }
}
__device__ __forceinline__ void cpa16s(uint32_t daddr, const void* src) {
    asm volatile("cp.async.cg.shared.global [%0], [%1], 16;\n" :: "r"(daddr), "l"(src) : "memory");
}
__device__ __forceinline__ void cp_commit() { asm volatile("cp.async.commit_group;\n" ::: "memory"); }
__device__ __forceinline__ void cp_wait1()  { asm volatile("cp.async.wait_group 1;\n" ::: "memory"); }
__device__ __forceinline__ void cp_wait0()  { asm volatile("cp.async.wait_group 0;\n" ::: "memory"); }

__device__ __forceinline__ void ldsm_x4(uint32_t* r, uint32_t a) {
    asm volatile("ldmatrix.sync.aligned.m8n8.x4.shared.b16 {%0,%1,%2,%3}, [%4];\n"
                 : "=r"(r[0]), "=r"(r[1]), "=r"(r[2]), "=r"(r[3]) : "r"(a));
}
__device__ __forceinline__ void ldsm_x4_p(uint32_t* r, const void* p) {
    unsigned a = (unsigned)__cvta_generic_to_shared(p);
    ldsm_x4(r, a);
}
__device__ __forceinline__ void ldsm_x4_t(uint32_t* r, uint32_t a) {
    asm volatile("ldmatrix.sync.aligned.m8n8.x4.trans.shared.b16 {%0,%1,%2,%3}, [%4];\n"
                 : "=r"(r[0]), "=r"(r[1]), "=r"(r[2]), "=r"(r[3]) : "r"(a));
}
__device__ __forceinline__ void ldsm_x2_t(uint32_t* r, const void* p) {
    unsigned a = (unsigned)__cvta_generic_to_shared(p);
    asm volatile("ldmatrix.sync.aligned.m8n8.x2.trans.shared.b16 {%0,%1}, [%2];\n"
                 : "=r"(r[0]), "=r"(r[1]) : "r"(a));
}
__device__ __forceinline__ void mma_bf16(float& d0, float& d1, float& d2, float& d3,
                                         const uint32_t a[4], const uint32_t b[2]) {
    asm volatile("mma.sync.aligned.m16n8k16.row.col.f32.bf16.bf16.f32 "
                 "{%0,%1,%2,%3}, {%4,%5,%6,%7}, {%8,%9}, {%0,%1,%2,%3};\n"
                 : "+f"(d0), "+f"(d1), "+f"(d2), "+f"(d3)
                 : "r"(a[0]), "r"(a[1]), "r"(a[2]), "r"(a[3]), "r"(b[0]), "r"(b[1]));
}
__device__ __forceinline__ float tanh_fast(float x) {
    float y; asm("tanh.approx.f32 %0, %1;" : "=f"(y) : "f"(x)); return y;
}
__device__ __forceinline__ float sigmoid_fast(float x) {
    return 1.0f / (1.0f + __expf(-x));
}
__device__ __forceinline__ void split2(float a, float b, uint32_t& h, uint32_t& l) {
    __nv_bfloat16 ha = __float2bfloat16(a), hb = __float2bfloat16(b);
    float la = a - __bfloat162float(ha);
    float lb = b - __bfloat162float(hb);
    __nv_bfloat162 H(ha, hb), L(__float2bfloat16(la), __float2bfloat16(lb));
    h = *reinterpret_cast<uint32_t*>(&H);
    l = *reinterpret_cast<uint32_t*>(&L);
}

// ---------------------------------------------------------------------------
// Preprocessing
// ---------------------------------------------------------------------------
// 16 floats per thread -> 2x16B hi + 2x16B lo
__global__ void split16_kernel(const float4* __restrict__ src,
                               uint4* __restrict__ hi, uint4* __restrict__ lo, int n16) {
    int i = blockIdx.x * blockDim.x + threadIdx.x;
    if (i >= n16) return;
    float4 a[4];
#pragma unroll
    for (int q = 0; q < 4; q++) a[q] = src[4 * i + q];
#pragma unroll
    for (int q = 0; q < 2; q++) {
        uint4 H, L;
        split2(a[2*q].x,   a[2*q].y,   H.x, L.x);
        split2(a[2*q].z,   a[2*q].w,   H.y, L.y);
        split2(a[2*q+1].x, a[2*q+1].y, H.z, L.z);
        split2(a[2*q+1].z, a[2*q+1].w, H.w, L.w);
        hi[2 * i + q] = H;
        lo[2 * i + q] = L;
    }
}

__global__ void transpose_split_kernel(const float* __restrict__ x,
                                       __nv_bfloat16* __restrict__ hi,
                                       __nv_bfloat16* __restrict__ lo) {
    int idx = blockIdx.x * blockDim.x + threadIdx.x;
    if (idx >= MROWS * FEAD) return;
    int f = idx % FEAD;
    int m = idx / FEAD;
    int b = m % BSZ;
    int t = m / BSZ;
    float v = x[((size_t)b * TSZ + t) * FEAD + f];
    __nv_bfloat16 h = __float2bfloat16(v);
    hi[idx] = h;
    lo[idx] = __float2bfloat16(v - __bfloat162float(h));
}

__global__ void zeropad_kernel(__nv_bfloat16* __restrict__ hi, __nv_bfloat16* __restrict__ lo) {
    int i = blockIdx.x * blockDim.x + threadIdx.x;
    int n = (MPAD - MROWS) * HDIM / 2;
    if (i >= n) return;
    reinterpret_cast<uint32_t*>(hi + (size_t)MROWS * HDIM)[i] = 0u;
    reinterpret_cast<uint32_t*>(lo + (size_t)MROWS * HDIM)[i] = 0u;
}

// ---------------------------------------------------------------------------
// U-GEMM (R10 version): pre-split bf16 operands, cp.async staging.
// BM=128, BN=192, BK=32, 384 threads (4x3 warps, 32x64 warp tile).
// ---------------------------------------------------------------------------
#define UK   1024
#define UN   3072
#define UBM  128
#define UBN  192
#define UBK  32
#define UNIT (UK / UBK)
#define UA_PB   (UBM * 40 * 2)
#define UB_PB   (UBK * 200 * 2)
#define U_SM_AH 0
#define U_SM_AL (U_SM_AH + 2 * UA_PB)
#define U_SM_BH (U_SM_AL + 2 * UA_PB)
#define U_SM_BL (U_SM_BH + 2 * UB_PB)
#define U_SM_TOTAL (U_SM_BL + 2 * UB_PB)   // 92160

__global__ __launch_bounds__(384, 1)
void u_gemm_kernel(const __nv_bfloat16* __restrict__ Ahi,
                   const __nv_bfloat16* __restrict__ Alo,
                   const __nv_bfloat16* __restrict__ Bhi,
                   const __nv_bfloat16* __restrict__ Blo,
                   float* __restrict__ U) {
    extern __shared__ char dsm[];
    uint32_t smem;
    asm("{ .reg .u64 t; cvta.to.shared.u64 t, %1; cvt.u32.u64 %0, t; }"
        : "=r"(smem) : "l"(dsm));

    const int tid  = threadIdx.x;
    const int warp = tid >> 5;
    const int lane = tid & 31;
    const int wrow = warp / 3;
    const int wcol = warp % 3;
    const int row0 = blockIdx.y * UBM;
    const int col0 = blockIdx.x * UBN;

    float acc[2][4][2][4];
#pragma unroll
    for (int a = 0; a < 2; a++)
#pragma unroll
        for (int b = 0; b < 4; b++)
#pragma unroll
            for (int c = 0; c < 2; c++)
#pragma unroll
                for (int d = 0; d < 4; d++) acc[a][b][c][d] = 0.0f;

    auto stage = [&](int it, int buf) {
        const int k0 = it * UBK;
#pragma unroll
        for (int i = 0; i < 3; i++) {
            int idx = tid + i * 384;
            if (idx < 1024) {
                int part = idx >> 9;
                int c = idx & 511;
                int r = c >> 2, kc = c & 3;
                uint32_t daddr = smem + (part ? U_SM_AL : U_SM_AH) + buf * UA_PB
                               + r * 80 + kc * 16;
                const __nv_bfloat16* src = part ? Alo : Ahi;
                cpa16s(daddr, src + (size_t)(row0 + r) * UK + k0 + kc * 8);
            }
        }
#pragma unroll
        for (int i = 0; i < 4; i++) {
            int idx = tid + i * 384;
            int part = idx >= 768;
            int c = part ? idx - 768 : idx;
            int r = c / 24, nc = c % 24;
            uint32_t daddr = smem + (part ? U_SM_BL : U_SM_BH) + buf * UB_PB
                           + r * 400 + nc * 16;
            const __nv_bfloat16* src = part ? Blo : Bhi;
            cpa16s(daddr, src + (size_t)(k0 + r) * UN + col0 + nc * 8);
        }
    };

    stage(0, 0);
    cp_commit();

    for (int it = 0; it < UNIT; ++it) {
        if (it + 1 < UNIT) {
            stage(it + 1, (it + 1) & 1);
            cp_commit();
            cp_wait1();
        } else {
            cp_wait0();
        }
        __syncthreads();
        const int buf = it & 1;

#pragma unroll
        for (int kk = 0; kk < 2; kk++) {
            uint32_t ah[2][4], al[2][4], bh[4][4], bl[4][4];
#pragma unroll
            for (int mt = 0; mt < 2; mt++) {
                uint32_t off = (uint32_t)((wrow * 32 + mt * 16 + (lane & 15)) * 80
                             + (kk * 16 + ((lane >> 4) << 3)) * 2) + buf * UA_PB;
                ldsm_x4(ah[mt], smem + U_SM_AH + off);
                ldsm_x4(al[mt], smem + U_SM_AL + off);
            }
#pragma unroll
            for (int nt = 0; nt < 4; nt++) {
                uint32_t off = (uint32_t)((kk * 16 + (lane & 15)) * 400
                             + (wcol * 64 + nt * 16 + ((lane >> 4) << 3)) * 2) + buf * UB_PB;
                ldsm_x4_t(bh[nt], smem + U_SM_BH + off);
                ldsm_x4_t(bl[nt], smem + U_SM_BL + off);
            }
#pragma unroll
            for (int mt = 0; mt < 2; mt++) {
#pragma unroll
                for (int nt = 0; nt < 4; nt++) {
#pragma unroll
                    for (int h8 = 0; h8 < 2; h8++) {
                        float* d = acc[mt][nt][h8];
                        mma_bf16(d[0], d[1], d[2], d[3], ah[mt], &bh[nt][h8 * 2]);
                        mma_bf16(d[0], d[1], d[2], d[3], ah[mt], &bl[nt][h8 * 2]);
                        mma_bf16(d[0], d[1], d[2], d[3], al[mt], &bh[nt][h8 * 2]);
                    }
                }
            }
        }
        __syncthreads();
    }

#pragma unroll
    for (int mt = 0; mt < 2; mt++) {
#pragma unroll
        for (int half = 0; half < 2; half++) {
            int row = row0 + wrow * 32 + mt * 16 + (lane >> 2) + half * 8;
            if (row >= MROWS) continue;
            float* dst = U + (size_t)row * UN;
#pragma unroll
            for (int nt = 0; nt < 4; nt++) {
#pragma unroll
                for (int h8 = 0; h8 < 2; h8++) {
                    int col = col0 + wcol * 64 + nt * 16 + h8 * 8 + ((lane & 3) << 1);
                    float2 v;
                    v.x = acc[mt][nt][h8][half * 2 + 0];
                    v.y = acc[mt][nt][h8][half * 2 + 1];
                    *reinterpret_cast<float2*>(dst + col) = v;
                }
            }
        }
    }
}

// ---------------------------------------------------------------------------
// Dense GEMM (R10 version)
// ---------------------------------------------------------------------------
#define BM 64
#define BN 128
#define BK 16

template<int RELU, int REMAP, int WF32, int WSPLIT>
__global__ __launch_bounds__(256, 2)
void mma_gemm(const __nv_bfloat16* __restrict__ Ahi, const __nv_bfloat16* __restrict__ Alo,
              const __nv_bfloat16* __restrict__ Bhi, const __nv_bfloat16* __restrict__ Blo,
              const float* __restrict__ bias,
              float* __restrict__ Cf,
              __nv_bfloat16* __restrict__ Chi, __nv_bfloat16* __restrict__ Clo,
              int M, int K, int N) {
    __shared__ __nv_bfloat16 sAh[2][BM][24];
    __shared__ __nv_bfloat16 sAl[2][BM][24];
    __shared__ __nv_bfloat16 sBh[2][BK][136];
    __shared__ __nv_bfloat16 sBl[2][BK][136];

    const int tid  = threadIdx.x;
    const int lane = tid & 31;
    const int warp = tid >> 5;
    const int wm = warp >> 2;
    const int wn = warp & 3;
    const int row0 = blockIdx.y * BM;
    const int col0 = blockIdx.x * BN;
    const bool nAligned = ((N & 7) == 0);

    const int a_part = tid >> 7;
    const int a_m    = (tid & 127) >> 1;
    const int a_half = tid & 1;
    const int b_kr   = tid >> 4;
    const int b_ch   = tid & 15;

    float acc[2][4][4];
#pragma unroll
    for (int mt = 0; mt < 2; mt++)
#pragma unroll
        for (int nt = 0; nt < 4; nt++)
#pragma unroll
            for (int j = 0; j < 4; j++) acc[mt][nt][j] = 0.0f;

    const int NTILES = (K + BK - 1) / BK;

    auto stage = [&](int k0, int buf) {
        {
            const __nv_bfloat16* src = a_part ? Alo : Ahi;
            __nv_bfloat16* dst = a_part ? &sAl[buf][a_m][a_half * 8]
                                        : &sAh[buf][a_m][a_half * 8];
            int gr = row0 + a_m;
            int gk = k0 + a_half * 8;
            bool p = (gr < M) && (gk < K);
            cpa16(dst, src + (size_t)gr * K + gk, p);
        }
        {
            int gk = k0 + b_kr;
            int gn = col0 + b_ch * 8;
            if (nAligned) {
                bool p = (gk < K) && (gn < N);
                cpa16(&sBh[buf][b_kr][b_ch * 8], Bhi + (size_t)gk * N + gn, p);
                cpa16(&sBl[buf][b_kr][b_ch * 8], Blo + (size_t)gk * N + gn, p);
            } else {
#pragma unroll
                for (int j = 0; j < 8; j++) {
                    int c = gn + j;
                    bool p = (gk < K) && (c < N);
                    sBh[buf][b_kr][b_ch * 8 + j] = p ? Bhi[(size_t)gk * N + c] : __nv_bfloat16(0.0f);
                    sBl[buf][b_kr][b_ch * 8 + j] = p ? Blo[(size_t)gk * N + c] : __nv_bfloat16(0.0f);
                }
            }
        }
    };

    stage(0, 0);
    cp_commit();

    for (int it = 0; it < NTILES; ++it) {
        if (it + 1 < NTILES) stage((it + 1) * BK, (it + 1) & 1);
        cp_commit();
        cp_wait1();
        __syncthreads();

        const int buf = it & 1;
        uint32_t ah[2][4], al[2][4], bh[4][2], bl[4][2];
#pragma unroll
        for (int mt = 0; mt < 2; mt++) {
            int r = wm * 32 + mt * 16 + (lane & 15);
            int kk = (lane >> 4) * 8;
            ldsm_x4_p(ah[mt], &sAh[buf][r][kk]);
            ldsm_x4_p(al[mt], &sAl[buf][r][kk]);
        }
#pragma unroll
        for (int nt = 0; nt < 4; nt++) {
            int n0 = wn * 32 + nt * 8;
            int kr = lane & 15;
            ldsm_x2_t(bh[nt], &sBh[buf][kr][n0]);
            ldsm_x2_t(bl[nt], &sBl[buf][kr][n0]);
        }
#pragma unroll
        for (int mt = 0; mt < 2; mt++) {
#pragma unroll
            for (int nt = 0; nt < 4; nt++) {
                float* d = acc[mt][nt];
                mma_bf16(d[0], d[1], d[2], d[3], ah[mt], bh[nt]);
                mma_bf16(d[0], d[1], d[2], d[3], ah[mt], bl[nt]);
                mma_bf16(d[0], d[1], d[2], d[3], al[mt], bh[nt]);
            }
        }
        __syncthreads();
    }

#pragma unroll
    for (int mt = 0; mt < 2; mt++) {
#pragma unroll
        for (int nt = 0; nt < 4; nt++) {
            int rbase = row0 + wm * 32 + mt * 16 + (lane >> 2);
            int cbase = col0 + wn * 32 + nt * 8 + ((lane & 3) << 1);
#pragma unroll
            for (int half = 0; half < 2; half++) {
                int row = rbase + half * 8;
                if (row >= M) continue;
                int orow = row;
                if (REMAP) {
                    int bb = row % BSZ;
                    int tt = row / BSZ;
                    orow = bb * TSZ + tt;
                }
#pragma unroll
                for (int j = 0; j < 2; j++) {
                    int col = cbase + j;
                    if (col >= N) continue;
                    float v = acc[mt][nt][half * 2 + j];
                    if (bias) v += bias[col];
                    if (RELU) v = fmaxf(v, 0.0f);
                    size_t o = (size_t)orow * N + col;
                    if (WF32) Cf[o] = v;
                    if (WSPLIT) {
                        __nv_bfloat16 h = __float2bfloat16(v);
                        Chi[o] = h;
                        Clo[o] = __float2bfloat16(v - __bfloat162float(h));
                    }
                }
            }
        }
    }
}

// ---------------------------------------------------------------------------
// SRU recurrence, float4-vectorized (R11 version — keep)
// ---------------------------------------------------------------------------
__global__ __launch_bounds__(128)
void sru_scan_kernel(const float* __restrict__ U, const float* __restrict__ c0,
                     const float* __restrict__ sb, float* __restrict__ h,
                     __nv_bfloat16* __restrict__ Ahi, __nv_bfloat16* __restrict__ Alo,
                     float* __restrict__ c_out) {
    int idx4 = blockIdx.x * 128 + threadIdx.x;
    if (idx4 >= BSZ * HDIM / 4) return;
    int e0 = idx4 * 4;
    int hh = e0 & (HDIM - 1);
    int b  = e0 >> 10;

    float4 c4  = *reinterpret_cast<const float4*>(c0 + e0);
    float4 bf4 = *reinterpret_cast<const float4*>(sb + hh);
    float4 br4 = *reinterpret_cast<const float4*>(sb + HDIM + hh);
    float* cc = reinterpret_cast<float*>(&c4);
    float* bfv = reinterpret_cast<float*>(&bf4);
    float* brv = reinterpret_cast<float*>(&br4);

#pragma unroll
    for (int t0 = 0; t0 < TSZ; t0 += 4) {
        float4 xf[4], uf[4], ur[4], hv[4];
#pragma unroll
        for (int i = 0; i < 4; i++) {
            int row = (t0 + i) * BSZ + b;
            const float* Ub = U + (size_t)row * (3 * HDIM) + hh;
            xf[i] = *reinterpret_cast<const float4*>(Ub);
            uf[i] = *reinterpret_cast<const float4*>(Ub + HDIM);
            ur[i] = *reinterpret_cast<const float4*>(Ub + 2 * HDIM);
            hv[i] = *reinterpret_cast<const float4*>(h + (size_t)row * HDIM + hh);
        }
#pragma unroll
        for (int i = 0; i < 4; i++) {
            float* xv = reinterpret_cast<float*>(&xf[i]);
            float* ufv = reinterpret_cast<float*>(&uf[i]);
            float* urv = reinterpret_cast<float*>(&ur[i]);
            float* hvv = reinterpret_cast<float*>(&hv[i]);
            float hn[4];
#pragma unroll
            for (int j = 0; j < 4; j++) {
                float f = sigmoid_fast(ufv[j] + bfv[j]);
                float r = sigmoid_fast(urv[j] + brv[j]);
                cc[j] = f * cc[j] + (1.0f - f) * xv[j];
                hn[j] = r * tanh_fast(cc[j]) + (1.0f - r) * hvv[j];
            }
            size_t o = (size_t)((t0 + i) * BSZ + b) * HDIM + hh;
            float4 hw = {hn[0], hn[1], hn[2], hn[3]};
            *reinterpret_cast<float4*>(h + o) = hw;
            uint2 Hp, Lp;
            split2(hn[0], hn[1], Hp.x, Lp.x);
            split2(hn[2], hn[3], Hp.y, Lp.y);
            *reinterpret_cast<uint2*>(Ahi + o) = Hp;
            *reinterpret_cast<uint2*>(Alo + o) = Lp;
        }
    }
    *reinterpret_cast<float4*>(c_out + e0) = c4;
}

// ---------------------------------------------------------------------------
extern "C" void kernel_launch(void* const* d_in, const int* in_sizes, int n_in,
                              void* d_out, int out_size) {
    const float* x      = (const float*)d_in[0];
    const float* hidden = (const float*)d_in[1];
    const float* W1     = (const float*)d_in[2];
    const float* b1     = (const float*)d_in[3];
    const float* sru_W  = (const float*)d_in[4];
    const float* sru_b  = (const float*)d_in[5];
    const float* W3     = (const float*)d_in[6];
    const float* b3     = (const float*)d_in[7];
    const float* W4     = (const float*)d_in[8];
    const float* b4     = (const float*)d_in[9];
    float* out = (float*)d_out;

    float *h, *U;
    __nv_bfloat16 *xthi, *xtlo, *Ahi, *Alo, *A2hi, *A2lo, *Wsmhi, *Wsmlo, *Wshi, *Wslo;
    cudaGetSymbolAddress((void**)&h,    g_h);
    cudaGetSymbolAddress((void**)&U,    g_U);
    cudaGetSymbolAddress((void**)&xthi, g_xthi);
    cudaGetSymbolAddress((void**)&xtlo, g_xtlo);
    cudaGetSymbolAddress((void**)&Ahi,  g_Ahi);
    cudaGetSymbolAddress((void**)&Alo,  g_Alo);
    cudaGetSymbolAddress((void**)&A2hi, g_A2hi);
    cudaGetSymbolAddress((void**)&A2lo, g_A2lo);
    cudaGetSymbolAddress((void**)&Wsmhi, g_Wsmhi);
    cudaGetSymbolAddress((void**)&Wsmlo, g_Wsmlo);
    cudaGetSymbolAddress((void**)&Wshi, g_Wshi);
    cudaGetSymbolAddress((void**)&Wslo, g_Wslo);

    static bool attr_set = false;
    if (!attr_set) {
        cudaFuncSetAttribute(u_gemm_kernel,
                             cudaFuncAttributeMaxDynamicSharedMemorySize, U_SM_TOTAL);
        attr_set = true;
    }

    // Preprocessing (per-call; deterministic)
    transpose_split_kernel<<<(MROWS * FEAD + 255) / 256, 256>>>(x, xthi, xtlo);
    split16_kernel<<<(N_W1 / 16 + 255) / 256, 256>>>((const float4*)W1, (uint4*)(Wsmhi + OFF_W1), (uint4*)(Wsmlo + OFF_W1), N_W1 / 16);
    split16_kernel<<<(N_W3 / 16 + 255) / 256, 256>>>((const float4*)W3, (uint4*)(Wsmhi + OFF_W3), (uint4*)(Wsmlo + OFF_W3), N_W3 / 16);
    split16_kernel<<<(N_W4 / 16 + 255) / 256, 256>>>((const float4*)W4, (uint4*)(Wsmhi + OFF_W4), (uint4*)(Wsmlo + OFF_W4), N_W4 / 16);
    split16_kernel<<<(N_SRU / 16 + 255) / 256, 256>>>((const float4*)sru_W, (uint4*)Wshi, (uint4*)Wslo, N_SRU / 16);
    zeropad_kernel<<<((MPAD - MROWS) * HDIM / 2 + 255) / 256, 256>>>(Ahi, Alo);

    const int GY = (MROWS + BM - 1) / BM;

    // Dense layer 1
    {
        dim3 grid((HDIM + BN - 1) / BN, GY);
        mma_gemm<0, 0, 1, 1><<<grid, 256>>>(xthi, xtlo, Wsmhi + OFF_W1, Wsmlo + OFF_W1,
                                            b1, h, Ahi, Alo, MROWS, FEAD, HDIM);
    }

    // SRU layers
    for (int l = 0; l < LNUM; l++) {
        size_t woff = (size_t)l * HDIM * 3 * HDIM;
        dim3 gridU(UN / UBN, MPAD / UBM);   // 16 x 7
        u_gemm_kernel<<<gridU, 384, U_SM_TOTAL>>>(Ahi, Alo, Wshi + woff, Wslo + woff, U);
        sru_scan_kernel<<<(BSZ * HDIM / 4 + 127) / 128, 128>>>(
            U, hidden + (size_t)l * BSZ * HDIM, sru_b + (size_t)l * 2 * HDIM,
            h, Ahi, Alo, out + OUT_ELEMS + (size_t)l * BSZ * HDIM);
    }

    // Dense ReLU with row remap
    {
        dim3 grid((HDIM + BN - 1) / BN, GY);
        mma_gemm<1, 1, 0, 1><<<grid, 256>>>(Ahi, Alo, Wsmhi + OFF_W3, Wsmlo + OFF_W3,
                                            b3, nullptr, A2hi, A2lo, MROWS, HDIM, HDIM);
    }

    // Output projection
    {
        dim3 grid((OUTD + BN - 1) / BN, GY);
        mma_gemm<0, 0, 1, 0><<<grid, 256>>>(A2hi, A2lo, Wsmhi + OFF_W4, Wsmlo + OFF_W4,
                                            b4, out, nullptr, nullptr, MROWS, HDIM, OUTD);
    }
}

// round 14
// speedup vs baseline: 1.5274x; 1.0266x over previous
#include <cuda_runtime.h>
#include <cuda_bf16.h>
#include <cstdint>
#include <cstddef>

#define BSZ   40
#define TSZ   20
#define FEAD  200
#define HDIM  1024
#define OUTD  1095
#define LNUM  12
#define MROWS (BSZ * TSZ)          // 800
#define MPAD  896                  // 7 * 128
#define OUT_ELEMS (MROWS * OUTD)   // 876000

#define OFF_W1  0
#define N_W1    (FEAD * HDIM)
#define OFF_W3  (OFF_W1 + N_W1)
#define N_W3    (HDIM * HDIM)
#define OFF_W4  (OFF_W3 + N_W3)
#define N_W4    (HDIM * OUTD)
#define N_WSM   (OFF_W4 + N_W4)

// ---------------------------------------------------------------------------
// Scratch
// ---------------------------------------------------------------------------
__device__ __align__(16) float g_h [MROWS * HDIM];
__device__ __align__(16) float g_U [MROWS * 3 * HDIM];
__device__ __align__(16) __nv_bfloat16 g_xthi[MROWS * FEAD];
__device__ __align__(16) __nv_bfloat16 g_xtlo[MROWS * FEAD];
__device__ __align__(16) __nv_bfloat16 g_Ahi [MPAD * HDIM];
__device__ __align__(16) __nv_bfloat16 g_Alo [MPAD * HDIM];
__device__ __align__(16) __nv_bfloat16 g_A2hi[MROWS * HDIM];
__device__ __align__(16) __nv_bfloat16 g_A2lo[MROWS * HDIM];
__device__ __align__(16) __nv_bfloat16 g_Wsmhi[N_WSM];
__device__ __align__(16) __nv_bfloat16 g_Wsmlo[N_WSM];

// ---------------------------------------------------------------------------
// PTX helpers
// ---------------------------------------------------------------------------
__device__ __forceinline__ void cpa16(void* dst, const void* src, bool pred) {
    unsigned d = (unsigned)__cvta_generic_to_shared(dst);
    if (pred) {
        asm volatile("cp.async.cg.shared.global [%0], [%1], 16;\n" :: "r"(d), "l"(src) : "memory");
    } else {
        uint4 z = {0u, 0u, 0u, 0u};
        *reinterpret_cast<uint4*>(dst) = z;
    }
}
__device__ __forceinline__ void cpa16s(uint32_t daddr, const void* src) {
    asm volatile("cp.async.cg.shared.global [%0], [%1], 16;\n" :: "r"(daddr), "l"(src) : "memory");
}
__device__ __forceinline__ void cp_commit() { asm volatile("cp.async.commit_group;\n" ::: "memory"); }
__device__ __forceinline__ void cp_wait1()  { asm volatile("cp.async.wait_group 1;\n" ::: "memory"); }
__device__ __forceinline__ void cp_wait0()  { asm volatile("cp.async.wait_group 0;\n" ::: "memory"); }

__device__ __forceinline__ void ldsm_x4(uint32_t* r, uint32_t a) {
    asm volatile("ldmatrix.sync.aligned.m8n8.x4.shared.b16 {%0,%1,%2,%3}, [%4];\n"
                 : "=r"(r[0]), "=r"(r[1]), "=r"(r[2]), "=r"(r[3]) : "r"(a));
}
__device__ __forceinline__ void ldsm_x4_p(uint32_t* r, const void* p) {
    unsigned a = (unsigned)__cvta_generic_to_shared(p);
    ldsm_x4(r, a);
}
__device__ __forceinline__ void ldsm_x4_t(uint32_t* r, uint32_t a) {
    asm volatile("ldmatrix.sync.aligned.m8n8.x4.trans.shared.b16 {%0,%1,%2,%3}, [%4];\n"
                 : "=r"(r[0]), "=r"(r[1]), "=r"(r[2]), "=r"(r[3]) : "r"(a));
}
__device__ __forceinline__ void ldsm_x2_t(uint32_t* r, const void* p) {
    unsigned a = (unsigned)__cvta_generic_to_shared(p);
    asm volatile("ldmatrix.sync.aligned.m8n8.x2.trans.shared.b16 {%0,%1}, [%2];\n"
                 : "=r"(r[0]), "=r"(r[1]) : "r"(a));
}
__device__ __forceinline__ void mma_bf16(float& d0, float& d1, float& d2, float& d3,
                                         const uint32_t a[4], const uint32_t b[2]) {
    asm volatile("mma.sync.aligned.m16n8k16.row.col.f32.bf16.bf16.f32 "
                 "{%0,%1,%2,%3}, {%4,%5,%6,%7}, {%8,%9}, {%0,%1,%2,%3};\n"
                 : "+f"(d0), "+f"(d1), "+f"(d2), "+f"(d3)
                 : "r"(a[0]), "r"(a[1]), "r"(a[2]), "r"(a[3]), "r"(b[0]), "r"(b[1]));
}
__device__ __forceinline__ float tanh_fast(float x) {
    float y; asm("tanh.approx.f32 %0, %1;" : "=f"(y) : "f"(x)); return y;
}
__device__ __forceinline__ float sigmoid_fast(float x) {
    return 1.0f / (1.0f + __expf(-x));
}
__device__ __forceinline__ void split2(float a, float b, uint32_t& h, uint32_t& l) {
    __nv_bfloat16 ha = __float2bfloat16(a), hb = __float2bfloat16(b);
    float la = a - __bfloat162float(ha);
    float lb = b - __bfloat162float(hb);
    __nv_bfloat162 H(ha, hb), L(__float2bfloat16(la), __float2bfloat16(lb));
    h = *reinterpret_cast<uint32_t*>(&H);
    l = *reinterpret_cast<uint32_t*>(&L);
}

// ---------------------------------------------------------------------------
// Preprocessing (small weights only — sru_W conversion is fused into u_gemm)
// ---------------------------------------------------------------------------
__global__ void split8_kernel(const float4* __restrict__ src,
                              uint4* __restrict__ hi, uint4* __restrict__ lo, int n8) {
    int i = blockIdx.x * blockDim.x + threadIdx.x;
    if (i >= n8) return;
    float4 a = src[2 * i];
    float4 b = src[2 * i + 1];
    uint4 H, L;
    split2(a.x, a.y, H.x, L.x);
    split2(a.z, a.w, H.y, L.y);
    split2(b.x, b.y, H.z, L.z);
    split2(b.z, b.w, H.w, L.w);
    hi[i] = H;
    lo[i] = L;
}

__global__ void transpose_split_kernel(const float* __restrict__ x,
                                       __nv_bfloat16* __restrict__ hi,
                                       __nv_bfloat16* __restrict__ lo) {
    int idx = blockIdx.x * blockDim.x + threadIdx.x;
    if (idx >= MROWS * FEAD) return;
    int f = idx % FEAD;
    int m = idx / FEAD;
    int b = m % BSZ;
    int t = m / BSZ;
    float v = x[((size_t)b * TSZ + t) * FEAD + f];
    __nv_bfloat16 h = __float2bfloat16(v);
    hi[idx] = h;
    lo[idx] = __float2bfloat16(v - __bfloat162float(h));
}

__global__ void zeropad_kernel(__nv_bfloat16* __restrict__ hi, __nv_bfloat16* __restrict__ lo) {
    int i = blockIdx.x * blockDim.x + threadIdx.x;
    int n = (MPAD - MROWS) * HDIM / 2;
    if (i >= n) return;
    reinterpret_cast<uint32_t*>(hi + (size_t)MROWS * HDIM)[i] = 0u;
    reinterpret_cast<uint32_t*>(lo + (size_t)MROWS * HDIM)[i] = 0u;
}

// ---------------------------------------------------------------------------
// U-GEMM: U[800,3072] = A[.,1024] @ W[1024,3072], W read as raw fp32 and
// split to bf16 hi/lo in SMEM (cp.async f32 staging -> convert one iter ahead).
// BM=128, BN=192, BK=32, 384 threads (4x3 warps, 32x64 warp tile).
// ---------------------------------------------------------------------------
#define UK   1024
#define UN   3072
#define UBM  128
#define UBN  192
#define UBK  32
#define UNIT (UK / UBK)            // 32
#define UA_PB    (UBM * 40 * 2)    // 10240 B  (A per part per buf)
#define UB_PB    (UBK * 200 * 2)   // 12800 B  (B bf16 per part per buf)
#define UF_PB    (UBK * 800)       // 25600 B  (B f32 stage per buf, row stride 800)
#define U_SM_AH  0
#define U_SM_AL  (U_SM_AH + 2 * UA_PB)     // 20480
#define U_SM_BH  (U_SM_AL + 2 * UA_PB)     // 40960
#define U_SM_BL  (U_SM_BH + 2 * UB_PB)     // 66560
#define U_SM_F32 (U_SM_BL + 2 * UB_PB)     // 92160
#define U_SM_TOTAL (U_SM_F32 + 2 * UF_PB)  // 143360

__global__ __launch_bounds__(384, 1)
void u_gemm_kernel(const __nv_bfloat16* __restrict__ Ahi,
                   const __nv_bfloat16* __restrict__ Alo,
                   const float* __restrict__ Bf,
                   float* __restrict__ U) {
    extern __shared__ char dsm[];
    uint32_t smem;
    asm("{ .reg .u64 t; cvta.to.shared.u64 t, %1; cvt.u32.u64 %0, t; }"
        : "=r"(smem) : "l"(dsm));

    const int tid  = threadIdx.x;
    const int warp = tid >> 5;
    const int lane = tid & 31;
    const int wrow = warp / 3;
    const int wcol = warp % 3;
    const int row0 = blockIdx.y * UBM;
    const int col0 = blockIdx.x * UBN;

    float acc[2][4][2][4];
#pragma unroll
    for (int a = 0; a < 2; a++)
#pragma unroll
        for (int b = 0; b < 4; b++)
#pragma unroll
            for (int c = 0; c < 2; c++)
#pragma unroll
                for (int d = 0; d < 4; d++) acc[a][b][c][d] = 0.0f;

    // stage A (bf16 hi/lo via cp.async) and B f32 (cp.async) for chunk it
    auto stageAB = [&](int it, int buf) {
        const int k0 = it * UBK;
        // A: 1024 chunks of 16B (512 hi + 512 lo)
#pragma unroll
        for (int i = 0; i < 3; i++) {
            int idx = tid + i * 384;
            if (idx < 1024) {
                int part = idx >> 9;
                int c = idx & 511;
                int r = c >> 2, kc = c & 3;
                uint32_t daddr = smem + (part ? U_SM_AL : U_SM_AH) + buf * UA_PB
                               + r * 80 + kc * 16;
                const __nv_bfloat16* src = part ? Alo : Ahi;
                cpa16s(daddr, src + (size_t)(row0 + r) * UK + k0 + kc * 8);
            }
        }
        // B f32: 32 rows x 48 float4 = 1536 chunks; 4 per thread
#pragma unroll
        for (int i = 0; i < 4; i++) {
            int c = tid + i * 384;
            int r = c / 48, f4 = c % 48;
            uint32_t daddr = smem + U_SM_F32 + buf * UF_PB + r * 800 + f4 * 16;
            cpa16s(daddr, Bf + (size_t)(it * UBK + r) * UN + col0 + f4 * 4);
        }
    };

    // convert f32 stage[buf] -> bf16 hi/lo tiles[buf]; 16 floats per thread
    const int cv_r = tid / 12;        // 0..31
    const int cv_g = tid % 12;        // 16-float group within row
    auto convert = [&](int buf) {
        const char* srcb = dsm + U_SM_F32 + buf * UF_PB + cv_r * 800 + cv_g * 64;
        float4 f[4];
#pragma unroll
        for (int q = 0; q < 4; q++)
            f[q] = *reinterpret_cast<const float4*>(srcb + q * 16);
        char* dh = dsm + U_SM_BH + buf * UB_PB + cv_r * 400 + cv_g * 32;
        char* dl = dsm + U_SM_BL + buf * UB_PB + cv_r * 400 + cv_g * 32;
#pragma unroll
        for (int q = 0; q < 2; q++) {
            uint4 H, L;
            split2(f[2*q].x,   f[2*q].y,   H.x, L.x);
            split2(f[2*q].z,   f[2*q].w,   H.y, L.y);
            split2(f[2*q+1].x, f[2*q+1].y, H.z, L.z);
            split2(f[2*q+1].z, f[2*q+1].w, H.w, L.w);
            *reinterpret_cast<uint4*>(dh + q * 16) = H;
            *reinterpret_cast<uint4*>(dl + q * 16) = L;
        }
    };

    // Prologue: stage(0) -> convert(0) -> stage(1)
    stageAB(0, 0);
    cp_commit();
    cp_wait0();
    __syncthreads();
    convert(0);
    stageAB(1, 1);
    cp_commit();
    __syncthreads();   // converted B(0) visible to all warps

    for (int it = 0; it < UNIT; ++it) {
        const int buf = it & 1;

        // ---- MMA on A[buf], Bbf[buf] ----
#pragma unroll
        for (int kk = 0; kk < 2; kk++) {
            uint32_t ah[2][4], al[2][4], bh[4][4], bl[4][4];
#pragma unroll
            for (int mt = 0; mt < 2; mt++) {
                uint32_t off = (uint32_t)((wrow * 32 + mt * 16 + (lane & 15)) * 80
                             + (kk * 16 + ((lane >> 4) << 3)) * 2) + buf * UA_PB;
                ldsm_x4(ah[mt], smem + U_SM_AH + off);
                ldsm_x4(al[mt], smem + U_SM_AL + off);
            }
#pragma unroll
            for (int nt = 0; nt < 4; nt++) {
                uint32_t off = (uint32_t)((kk * 16 + (lane & 15)) * 400
                             + (wcol * 64 + nt * 16 + ((lane >> 4) << 3)) * 2) + buf * UB_PB;
                ldsm_x4_t(bh[nt], smem + U_SM_BH + off);
                ldsm_x4_t(bl[nt], smem + U_SM_BL + off);
            }
#pragma unroll
            for (int mt = 0; mt < 2; mt++) {
#pragma unroll
                for (int nt = 0; nt < 4; nt++) {
#pragma unroll
                    for (int h8 = 0; h8 < 2; h8++) {
                        float* d = acc[mt][nt][h8];
                        mma_bf16(d[0], d[1], d[2], d[3], ah[mt], &bh[nt][h8 * 2]);
                        mma_bf16(d[0], d[1], d[2], d[3], ah[mt], &bl[nt][h8 * 2]);
                        mma_bf16(d[0], d[1], d[2], d[3], al[mt], &bh[nt][h8 * 2]);
                    }
                }
            }
        }

        // ---- Tail: convert next chunk, prefetch chunk after ----
        if (it + 1 < UNIT) {
            const int nb = (it + 1) & 1;
            __syncthreads();      // all reads of A[buf] / f32stage[buf] done
            cp_wait0();           // data for (it+1) arrived
            convert(nb);
            if (it + 2 < UNIT) {
                stageAB(it + 2, buf);
                cp_commit();
            }
            __syncthreads();      // converted B(it+1) visible
        }
    }

    // Epilogue
#pragma unroll
    for (int mt = 0; mt < 2; mt++) {
#pragma unroll
        for (int half = 0; half < 2; half++) {
            int row = row0 + wrow * 32 + mt * 16 + (lane >> 2) + half * 8;
            if (row >= MROWS) continue;
            float* dst = U + (size_t)row * UN;
#pragma unroll
            for (int nt = 0; nt < 4; nt++) {
#pragma unroll
                for (int h8 = 0; h8 < 2; h8++) {
                    int col = col0 + wcol * 64 + nt * 16 + h8 * 8 + ((lane & 3) << 1);
                    float2 v;
                    v.x = acc[mt][nt][h8][half * 2 + 0];
                    v.y = acc[mt][nt][h8][half * 2 + 1];
                    *reinterpret_cast<float2*>(dst + col) = v;
                }
            }
        }
    }
}

// ---------------------------------------------------------------------------
// Dense GEMM (R10 version, pre-split weights)
// ---------------------------------------------------------------------------
#define BM 64
#define BN 128
#define BK 16

template<int RELU, int REMAP, int WF32, int WSPLIT>
__global__ __launch_bounds__(256, 2)
void mma_gemm(const __nv_bfloat16* __restrict__ Ahi, const __nv_bfloat16* __restrict__ Alo,
              const __nv_bfloat16* __restrict__ Bhi, const __nv_bfloat16* __restrict__ Blo,
              const float* __restrict__ bias,
              float* __restrict__ Cf,
              __nv_bfloat16* __restrict__ Chi, __nv_bfloat16* __restrict__ Clo,
              int M, int K, int N) {
    __shared__ __nv_bfloat16 sAh[2][BM][24];
    __shared__ __nv_bfloat16 sAl[2][BM][24];
    __shared__ __nv_bfloat16 sBh[2][BK][136];
    __shared__ __nv_bfloat16 sBl[2][BK][136];

    const int tid  = threadIdx.x;
    const int lane = tid & 31;
    const int warp = tid >> 5;
    const int wm = warp >> 2;
    const int wn = warp & 3;
    const int row0 = blockIdx.y * BM;
    const int col0 = blockIdx.x * BN;
    const bool nAligned = ((N & 7) == 0);

    const int a_part = tid >> 7;
    const int a_m    = (tid & 127) >> 1;
    const int a_half = tid & 1;
    const int b_kr   = tid >> 4;
    const int b_ch   = tid & 15;

    float acc[2][4][4];
#pragma unroll
    for (int mt = 0; mt < 2; mt++)
#pragma unroll
        for (int nt = 0; nt < 4; nt++)
#pragma unroll
            for (int j = 0; j < 4; j++) acc[mt][nt][j] = 0.0f;

    const int NTILES = (K + BK - 1) / BK;

    auto stage = [&](int k0, int buf) {
        {
            const __nv_bfloat16* src = a_part ? Alo : Ahi;
            __nv_bfloat16* dst = a_part ? &sAl[buf][a_m][a_half * 8]
                                        : &sAh[buf][a_m][a_half * 8];
            int gr = row0 + a_m;
            int gk = k0 + a_half * 8;
            bool p = (gr < M) && (gk < K);
            cpa16(dst, src + (size_t)gr * K + gk, p);
        }
        {
            int gk = k0 + b_kr;
            int gn = col0 + b_ch * 8;
            if (nAligned) {
                bool p = (gk < K) && (gn < N);
                cpa16(&sBh[buf][b_kr][b_ch * 8], Bhi + (size_t)gk * N + gn, p);
                cpa16(&sBl[buf][b_kr][b_ch * 8], Blo + (size_t)gk * N + gn, p);
            } else {
#pragma unroll
                for (int j = 0; j < 8; j++) {
                    int c = gn + j;
                    bool p = (gk < K) && (c < N);
                    sBh[buf][b_kr][b_ch * 8 + j] = p ? Bhi[(size_t)gk * N + c] : __nv_bfloat16(0.0f);
                    sBl[buf][b_kr][b_ch * 8 + j] = p ? Blo[(size_t)gk * N + c] : __nv_bfloat16(0.0f);
                }
            }
        }
    };

    stage(0, 0);
    cp_commit();

    for (int it = 0; it < NTILES; ++it) {
        if (it + 1 < NTILES) stage((it + 1) * BK, (it + 1) & 1);
        cp_commit();
        cp_wait1();
        __syncthreads();

        const int buf = it & 1;
        uint32_t ah[2][4], al[2][4], bh[4][2], bl[4][2];
#pragma unroll
        for (int mt = 0; mt < 2; mt++) {
            int r = wm * 32 + mt * 16 + (lane & 15);
            int kk = (lane >> 4) * 8;
            ldsm_x4_p(ah[mt], &sAh[buf][r][kk]);
            ldsm_x4_p(al[mt], &sAl[buf][r][kk]);
        }
#pragma unroll
        for (int nt = 0; nt < 4; nt++) {
            int n0 = wn * 32 + nt * 8;
            int kr = lane & 15;
            ldsm_x2_t(bh[nt], &sBh[buf][kr][n0]);
            ldsm_x2_t(bl[nt], &sBl[buf][kr][n0]);
        }
#pragma unroll
        for (int mt = 0; mt < 2; mt++) {
#pragma unroll
            for (int nt = 0; nt < 4; nt++) {
                float* d = acc[mt][nt];
                mma_bf16(d[0], d[1], d[2], d[3], ah[mt], bh[nt]);
                mma_bf16(d[0], d[1], d[2], d[3], ah[mt], bl[nt]);
                mma_bf16(d[0], d[1], d[2], d[3], al[mt], bh[nt]);
            }
        }
        __syncthreads();
    }

#pragma unroll
    for (int mt = 0; mt < 2; mt++) {
#pragma unroll
        for (int nt = 0; nt < 4; nt++) {
            int rbase = row0 + wm * 32 + mt * 16 + (lane >> 2);
            int cbase = col0 + wn * 32 + nt * 8 + ((lane & 3) << 1);
#pragma unroll
            for (int half = 0; half < 2; half++) {
                int row = rbase + half * 8;
                if (row >= M) continue;
                int orow = row;
                if (REMAP) {
                    int bb = row % BSZ;
                    int tt = row / BSZ;
                    orow = bb * TSZ + tt;
                }
#pragma unroll
                for (int j = 0; j < 2; j++) {
                    int col = cbase + j;
                    if (col >= N) continue;
                    float v = acc[mt][nt][half * 2 + j];
                    if (bias) v += bias[col];
                    if (RELU) v = fmaxf(v, 0.0f);
                    size_t o = (size_t)orow * N + col;
                    if (WF32) Cf[o] = v;
                    if (WSPLIT) {
                        __nv_bfloat16 h = __float2bfloat16(v);
                        Chi[o] = h;
                        Clo[o] = __float2bfloat16(v - __bfloat162float(h));
                    }
                }
            }
        }
    }
}

// ---------------------------------------------------------------------------
// SRU recurrence (R10 scalar version — known good)
// ---------------------------------------------------------------------------
__global__ __launch_bounds__(128)
void sru_scan_kernel(const float* __restrict__ U, const float* __restrict__ c0,
                     const float* __restrict__ sb, float* __restrict__ h,
                     __nv_bfloat16* __restrict__ Ahi, __nv_bfloat16* __restrict__ Alo,
                     float* __restrict__ c_out) {
    int idx = blockIdx.x * 128 + threadIdx.x;
    if (idx >= BSZ * HDIM) return;
    int hh = idx & (HDIM - 1);
    int b  = idx >> 10;
    float c  = c0[idx];
    float bf = sb[hh];
    float br = sb[HDIM + hh];
#pragma unroll
    for (int t0 = 0; t0 < TSZ; t0 += 5) {
        float xf[5], uf[5], ur[5], hv[5];
#pragma unroll
        for (int i = 0; i < 5; i++) {
            int row = (t0 + i) * BSZ + b;
            const float* Ur = U + (size_t)row * (3 * HDIM);
            xf[i] = Ur[hh];
            uf[i] = Ur[HDIM + hh];
            ur[i] = Ur[2 * HDIM + hh];
            hv[i] = h[(size_t)row * HDIM + hh];
        }
#pragma unroll
        for (int i = 0; i < 5; i++) {
            float f = sigmoid_fast(uf[i] + bf);
            float r = sigmoid_fast(ur[i] + br);
            c = f * c + (1.0f - f) * xf[i];
            float hn = r * tanh_fast(c) + (1.0f - r) * hv[i];
            size_t o = (size_t)((t0 + i) * BSZ + b) * HDIM + hh;
            h[o] = hn;
            __nv_bfloat16 hb = __float2bfloat16(hn);
            Ahi[o] = hb;
            Alo[o] = __float2bfloat16(hn - __bfloat162float(hb));
        }
    }
    c_out[idx] = c;
}

// ---------------------------------------------------------------------------
extern "C" void kernel_launch(void* const* d_in, const int* in_sizes, int n_in,
                              void* d_out, int out_size) {
    const float* x      = (const float*)d_in[0];
    const float* hidden = (const float*)d_in[1];
    const float* W1     = (const float*)d_in[2];
    const float* b1     = (const float*)d_in[3];
    const float* sru_W  = (const float*)d_in[4];
    const float* sru_b  = (const float*)d_in[5];
    const float* W3     = (const float*)d_in[6];
    const float* b3     = (const float*)d_in[7];
    const float* W4     = (const float*)d_in[8];
    const float* b4     = (const float*)d_in[9];
    float* out = (float*)d_out;

    float *h, *U;
    __nv_bfloat16 *xthi, *xtlo, *Ahi, *Alo, *A2hi, *A2lo, *Wsmhi, *Wsmlo;
    cudaGetSymbolAddress((void**)&h,    g_h);
    cudaGetSymbolAddress((void**)&U,    g_U);
    cudaGetSymbolAddress((void**)&xthi, g_xthi);
    cudaGetSymbolAddress((void**)&xtlo, g_xtlo);
    cudaGetSymbolAddress((void**)&Ahi,  g_Ahi);
    cudaGetSymbolAddress((void**)&Alo,  g_Alo);
    cudaGetSymbolAddress((void**)&A2hi, g_A2hi);
    cudaGetSymbolAddress((void**)&A2lo, g_A2lo);
    cudaGetSymbolAddress((void**)&Wsmhi, g_Wsmhi);
    cudaGetSymbolAddress((void**)&Wsmlo, g_Wsmlo);

    static bool attr_set = false;
    if (!attr_set) {
        cudaFuncSetAttribute(u_gemm_kernel,
                             cudaFuncAttributeMaxDynamicSharedMemorySize, U_SM_TOTAL);
        attr_set = true;
    }

    // Preprocessing: only small weights + input (sru_W fused into u_gemm)
    transpose_split_kernel<<<(MROWS * FEAD + 255) / 256, 256>>>(x, xthi, xtlo);
    split8_kernel<<<(N_W1 / 8 + 255) / 256, 256>>>((const float4*)W1, (uint4*)(Wsmhi + OFF_W1), (uint4*)(Wsmlo + OFF_W1), N_W1 / 8);
    split8_kernel<<<(N_W3 / 8 + 255) / 256, 256>>>((const float4*)W3, (uint4*)(Wsmhi + OFF_W3), (uint4*)(Wsmlo + OFF_W3), N_W3 / 8);
    split8_kernel<<<(N_W4 / 8 + 255) / 256, 256>>>((const float4*)W4, (uint4*)(Wsmhi + OFF_W4), (uint4*)(Wsmlo + OFF_W4), N_W4 / 8);
    zeropad_kernel<<<((MPAD - MROWS) * HDIM / 2 + 255) / 256, 256>>>(Ahi, Alo);

    const int GY = (MROWS + BM - 1) / BM;

    // Dense layer 1
    {
        dim3 grid((HDIM + BN - 1) / BN, GY);
        mma_gemm<0, 0, 1, 1><<<grid, 256>>>(xthi, xtlo, Wsmhi + OFF_W1, Wsmlo + OFF_W1,
                                            b1, h, Ahi, Alo, MROWS, FEAD, HDIM);
    }

    // SRU layers (u_gemm reads raw fp32 sru_W directly)
    for (int l = 0; l < LNUM; l++) {
        dim3 gridU(UN / UBN, MPAD / UBM);   // 16 x 7 = 112 blocks
        u_gemm_kernel<<<gridU, 384, U_SM_TOTAL>>>(Ahi, Alo,
                                                  sru_W + (size_t)l * HDIM * 3 * HDIM, U);
        sru_scan_kernel<<<(BSZ * HDIM + 127) / 128, 128>>>(
            U, hidden + (size_t)l * BSZ * HDIM, sru_b + (size_t)l * 2 * HDIM,
            h, Ahi, Alo, out + OUT_ELEMS + (size_t)l * BSZ * HDIM);
    }

    // Dense ReLU with row remap
    {
        dim3 grid((HDIM + BN - 1) / BN, GY);
        mma_gemm<1, 1, 0, 1><<<grid, 256>>>(Ahi, Alo, Wsmhi + OFF_W3, Wsmlo + OFF_W3,
                                            b3, nullptr, A2hi, A2lo, MROWS, HDIM, HDIM);
    }

    // Output projection
    {
        dim3 grid((OUTD + BN - 1) / BN, GY);
        mma_gemm<0, 0, 1, 0><<<grid, 256>>>(A2hi, A2lo, Wsmhi + OFF_W4, Wsmlo + OFF_W4,
                                            b4, out, nullptr, nullptr, MROWS, HDIM, OUTD);
    }
}

// round 15
// speedup vs baseline: 1.6396x; 1.0734x over previous
#include <cuda_runtime.h>
#include <cuda_bf16.h>
#include <cstdint>
#include <cstddef>

#define BSZ   40
#define TSZ   20
#define FEAD  200
#define HDIM  1024
#define OUTD  1095
#define LNUM  12
#define MROWS (BSZ * TSZ)          // 800
#define MPAD  896                  // 7 * 128
#define OUT_ELEMS (MROWS * OUTD)   // 876000

#define OFF_W1  0
#define N_W1    (FEAD * HDIM)
#define OFF_W3  (OFF_W1 + N_W1)
#define N_W3    (HDIM * HDIM)
#define OFF_W4  (OFF_W3 + N_W3)
#define N_W4    (HDIM * OUTD)
#define N_WSM   (OFF_W4 + N_W4)
#define N_SRU   (LNUM * HDIM * 3 * HDIM)

// ---------------------------------------------------------------------------
// Scratch
// ---------------------------------------------------------------------------
__device__ __align__(16) float g_h [MROWS * HDIM];
__device__ __align__(16) float g_U [MROWS * 3 * HDIM];
__device__ __align__(16) __nv_bfloat16 g_xthi[MROWS * FEAD];
__device__ __align__(16) __nv_bfloat16 g_xtlo[MROWS * FEAD];
__device__ __align__(16) __nv_bfloat16 g_Ahi [MPAD * HDIM];
__device__ __align__(16) __nv_bfloat16 g_Alo [MPAD * HDIM];
__device__ __align__(16) __nv_bfloat16 g_A2hi[MROWS * HDIM];
__device__ __align__(16) __nv_bfloat16 g_A2lo[MROWS * HDIM];
__device__ __align__(16) __nv_bfloat16 g_Wsmhi[N_WSM];
__device__ __align__(16) __nv_bfloat16 g_Wsmlo[N_WSM];
__device__ __align__(16) __nv_bfloat16 g_Wshi[N_SRU];
__device__ __align__(16) __nv_bfloat16 g_Wslo[N_SRU];

// ---------------------------------------------------------------------------
// PTX helpers
// ---------------------------------------------------------------------------
__device__ __forceinline__ void cpa16(void* dst, const void* src, bool pred) {
    unsigned d = (unsigned)__cvta_generic_to_shared(dst);
    if (pred) {
        asm volatile("cp.async.cg.shared.global [%0], [%1], 16;\n" :: "r"(d), "l"(src) : "memory");
    } else {
        uint4 z = {0u, 0u, 0u, 0u};
        *reinterpret_cast<uint4*>(dst) = z;
    }
}
__device__ __forceinline__ void cpa16s(uint32_t daddr, const void* src) {
    asm volatile("cp.async.cg.shared.global [%0], [%1], 16;\n" :: "r"(daddr), "l"(src) : "memory");
}
__device__ __forceinline__ void cp_commit() { asm volatile("cp.async.commit_group;\n" ::: "memory"); }
__device__ __forceinline__ void cp_wait1()  { asm volatile("cp.async.wait_group 1;\n" ::: "memory"); }
__device__ __forceinline__ void cp_wait0()  { asm volatile("cp.async.wait_group 0;\n" ::: "memory"); }

__device__ __forceinline__ void ldsm_x4(uint32_t* r, uint32_t a) {
    asm volatile("ldmatrix.sync.aligned.m8n8.x4.shared.b16 {%0,%1,%2,%3}, [%4];\n"
                 : "=r"(r[0]), "=r"(r[1]), "=r"(r[2]), "=r"(r[3]) : "r"(a));
}
__device__ __forceinline__ void ldsm_x4_p(uint32_t* r, const void* p) {
    unsigned a = (unsigned)__cvta_generic_to_shared(p);
    ldsm_x4(r, a);
}
__device__ __forceinline__ void ldsm_x4_t(uint32_t* r, uint32_t a) {
    asm volatile("ldmatrix.sync.aligned.m8n8.x4.trans.shared.b16 {%0,%1,%2,%3}, [%4];\n"
                 : "=r"(r[0]), "=r"(r[1]), "=r"(r[2]), "=r"(r[3]) : "r"(a));
}
__device__ __forceinline__ void ldsm_x2_t(uint32_t* r, const void* p) {
    unsigned a = (unsigned)__cvta_generic_to_shared(p);
    asm volatile("ldmatrix.sync.aligned.m8n8.x2.trans.shared.b16 {%0,%1}, [%2];\n"
                 : "=r"(r[0]), "=r"(r[1]) : "r"(a));
}
__device__ __forceinline__ void mma_bf16(float& d0, float& d1, float& d2, float& d3,
                                         const uint32_t a[4], const uint32_t b[2]) {
    asm volatile("mma.sync.aligned.m16n8k16.row.col.f32.bf16.bf16.f32 "
                 "{%0,%1,%2,%3}, {%4,%5,%6,%7}, {%8,%9}, {%0,%1,%2,%3};\n"
                 : "+f"(d0), "+f"(d1), "+f"(d2), "+f"(d3)
                 : "r"(a[0]), "r"(a[1]), "r"(a[2]), "r"(a[3]), "r"(b[0]), "r"(b[1]));
}
__device__ __forceinline__ float tanh_fast(float x) {
    float y; asm("tanh.approx.f32 %0, %1;" : "=f"(y) : "f"(x)); return y;
}
// sigmoid via tanh: 1 MUFU instead of EX2+RCP
__device__ __forceinline__ float sigmoid_fast(float x) {
    return 0.5f + 0.5f * tanh_fast(0.5f * x);
}

// Fast Ootomo split for a pair: hi = truncate-to-bf16 (PRMT, no cvt),
// lo = RN(v - hi) via one packed cvt.rn.bf16x2. Result packed bf16x2
// (a in low half, b in high half).
__device__ __forceinline__ void split2(float a, float b, uint32_t& h, uint32_t& l) {
    uint32_t ua = __float_as_uint(a);
    uint32_t ub = __float_as_uint(b);
    h = __byte_perm(ua, ub, 0x7632);                    // {a.hi16, b.hi16}
    float ha = __uint_as_float(ua & 0xFFFF0000u);
    float hb = __uint_as_float(ub & 0xFFFF0000u);
    float la = a - ha;                                  // exact
    float lb = b - hb;                                  // exact
    asm("cvt.rn.bf16x2.f32 %0, %1, %2;" : "=r"(l) : "f"(lb), "f"(la));
}

// ---------------------------------------------------------------------------
// Preprocessing
// ---------------------------------------------------------------------------
__global__ void split8_kernel(const float4* __restrict__ src,
                              uint4* __restrict__ hi, uint4* __restrict__ lo, int n8) {
    int i = blockIdx.x * blockDim.x + threadIdx.x;
    if (i >= n8) return;
    float4 a = src[2 * i];
    float4 b = src[2 * i + 1];
    uint4 H, L;
    split2(a.x, a.y, H.x, L.x);
    split2(a.z, a.w, H.y, L.y);
    split2(b.x, b.y, H.z, L.z);
    split2(b.z, b.w, H.w, L.w);
    hi[i] = H;
    lo[i] = L;
}

__global__ void transpose_split_kernel(const float* __restrict__ x,
                                       __nv_bfloat16* __restrict__ hi,
                                       __nv_bfloat16* __restrict__ lo) {
    int idx = blockIdx.x * blockDim.x + threadIdx.x;
    if (idx >= MROWS * FEAD) return;
    int f = idx % FEAD;
    int m = idx / FEAD;
    int b = m % BSZ;
    int t = m / BSZ;
    float v = x[((size_t)b * TSZ + t) * FEAD + f];
    uint32_t uv = __float_as_uint(v);
    uint16_t hbits = (uint16_t)(uv >> 16);               // truncation hi
    float hf = __uint_as_float(uv & 0xFFFF0000u);
    __nv_bfloat16 hb, lb;
    *reinterpret_cast<uint16_t*>(&hb) = hbits;
    lb = __float2bfloat16(v - hf);
    hi[idx] = hb;
    lo[idx] = lb;
}

__global__ void zeropad_kernel(__nv_bfloat16* __restrict__ hi, __nv_bfloat16* __restrict__ lo) {
    int i = blockIdx.x * blockDim.x + threadIdx.x;
    int n = (MPAD - MROWS) * HDIM / 2;
    if (i >= n) return;
    reinterpret_cast<uint32_t*>(hi + (size_t)MROWS * HDIM)[i] = 0u;
    reinterpret_cast<uint32_t*>(lo + (size_t)MROWS * HDIM)[i] = 0u;
}

// ---------------------------------------------------------------------------
// U-GEMM (R10 version, untouched): pre-split bf16 operands, cp.async staging.
// BM=128, BN=192, BK=32, 384 threads (4x3 warps, 32x64 warp tile).
// ---------------------------------------------------------------------------
#define UK   1024
#define UN   3072
#define UBM  128
#define UBN  192
#define UBK  32
#define UNIT (UK / UBK)
#define UA_PB   (UBM * 40 * 2)
#define UB_PB   (UBK * 200 * 2)
#define U_SM_AH 0
#define U_SM_AL (U_SM_AH + 2 * UA_PB)
#define U_SM_BH (U_SM_AL + 2 * UA_PB)
#define U_SM_BL (U_SM_BH + 2 * UB_PB)
#define U_SM_TOTAL (U_SM_BL + 2 * UB_PB)   // 92160

__global__ __launch_bounds__(384, 1)
void u_gemm_kernel(const __nv_bfloat16* __restrict__ Ahi,
                   const __nv_bfloat16* __restrict__ Alo,
                   const __nv_bfloat16* __restrict__ Bhi,
                   const __nv_bfloat16* __restrict__ Blo,
                   float* __restrict__ U) {
    extern __shared__ char dsm[];
    uint32_t smem;
    asm("{ .reg .u64 t; cvta.to.shared.u64 t, %1; cvt.u32.u64 %0, t; }"
        : "=r"(smem) : "l"(dsm));

    const int tid  = threadIdx.x;
    const int warp = tid >> 5;
    const int lane = tid & 31;
    const int wrow = warp / 3;
    const int wcol = warp % 3;
    const int row0 = blockIdx.y * UBM;
    const int col0 = blockIdx.x * UBN;

    float acc[2][4][2][4];
#pragma unroll
    for (int a = 0; a < 2; a++)
#pragma unroll
        for (int b = 0; b < 4; b++)
#pragma unroll
            for (int c = 0; c < 2; c++)
#pragma unroll
                for (int d = 0; d < 4; d++) acc[a][b][c][d] = 0.0f;

    auto stage = [&](int it, int buf) {
        const int k0 = it * UBK;
#pragma unroll
        for (int i = 0; i < 3; i++) {
            int idx = tid + i * 384;
            if (idx < 1024) {
                int part = idx >> 9;
                int c = idx & 511;
                int r = c >> 2, kc = c & 3;
                uint32_t daddr = smem + (part ? U_SM_AL : U_SM_AH) + buf * UA_PB
                               + r * 80 + kc * 16;
                const __nv_bfloat16* src = part ? Alo : Ahi;
                cpa16s(daddr, src + (size_t)(row0 + r) * UK + k0 + kc * 8);
            }
        }
#pragma unroll
        for (int i = 0; i < 4; i++) {
            int idx = tid + i * 384;
            int part = idx >= 768;
            int c = part ? idx - 768 : idx;
            int r = c / 24, nc = c % 24;
            uint32_t daddr = smem + (part ? U_SM_BL : U_SM_BH) + buf * UB_PB
                           + r * 400 + nc * 16;
            const __nv_bfloat16* src = part ? Blo : Bhi;
            cpa16s(daddr, src + (size_t)(k0 + r) * UN + col0 + nc * 8);
        }
    };

    stage(0, 0);
    cp_commit();

    for (int it = 0; it < UNIT; ++it) {
        if (it + 1 < UNIT) {
            stage(it + 1, (it + 1) & 1);
            cp_commit();
            cp_wait1();
        } else {
            cp_wait0();
        }
        __syncthreads();
        const int buf = it & 1;

#pragma unroll
        for (int kk = 0; kk < 2; kk++) {
            uint32_t ah[2][4], al[2][4], bh[4][4], bl[4][4];
#pragma unroll
            for (int mt = 0; mt < 2; mt++) {
                uint32_t off = (uint32_t)((wrow * 32 + mt * 16 + (lane & 15)) * 80
                             + (kk * 16 + ((lane >> 4) << 3)) * 2) + buf * UA_PB;
                ldsm_x4(ah[mt], smem + U_SM_AH + off);
                ldsm_x4(al[mt], smem + U_SM_AL + off);
            }
#pragma unroll
            for (int nt = 0; nt < 4; nt++) {
                uint32_t off = (uint32_t)((kk * 16 + (lane & 15)) * 400
                             + (wcol * 64 + nt * 16 + ((lane >> 4) << 3)) * 2) + buf * UB_PB;
                ldsm_x4_t(bh[nt], smem + U_SM_BH + off);
                ldsm_x4_t(bl[nt], smem + U_SM_BL + off);
            }
#pragma unroll
            for (int mt = 0; mt < 2; mt++) {
#pragma unroll
                for (int nt = 0; nt < 4; nt++) {
#pragma unroll
                    for (int h8 = 0; h8 < 2; h8++) {
                        float* d = acc[mt][nt][h8];
                        mma_bf16(d[0], d[1], d[2], d[3], ah[mt], &bh[nt][h8 * 2]);
                        mma_bf16(d[0], d[1], d[2], d[3], ah[mt], &bl[nt][h8 * 2]);
                        mma_bf16(d[0], d[1], d[2], d[3], al[mt], &bh[nt][h8 * 2]);
                    }
                }
            }
        }
        __syncthreads();
    }

#pragma unroll
    for (int mt = 0; mt < 2; mt++) {
#pragma unroll
        for (int half = 0; half < 2; half++) {
            int row = row0 + wrow * 32 + mt * 16 + (lane >> 2) + half * 8;
            if (row >= MROWS) continue;
            float* dst = U + (size_t)row * UN;
#pragma unroll
            for (int nt = 0; nt < 4; nt++) {
#pragma unroll
                for (int h8 = 0; h8 < 2; h8++) {
                    int col = col0 + wcol * 64 + nt * 16 + h8 * 8 + ((lane & 3) << 1);
                    float2 v;
                    v.x = acc[mt][nt][h8][half * 2 + 0];
                    v.y = acc[mt][nt][h8][half * 2 + 1];
                    *reinterpret_cast<float2*>(dst + col) = v;
                }
            }
        }
    }
}

// ---------------------------------------------------------------------------
// Dense GEMM (R10 version)
// ---------------------------------------------------------------------------
#define BM 64
#define BN 128
#define BK 16

template<int RELU, int REMAP, int WF32, int WSPLIT>
__global__ __launch_bounds__(256, 2)
void mma_gemm(const __nv_bfloat16* __restrict__ Ahi, const __nv_bfloat16* __restrict__ Alo,
              const __nv_bfloat16* __restrict__ Bhi, const __nv_bfloat16* __restrict__ Blo,
              const float* __restrict__ bias,
              float* __restrict__ Cf,
              __nv_bfloat16* __restrict__ Chi, __nv_bfloat16* __restrict__ Clo,
              int M, int K, int N) {
    __shared__ __nv_bfloat16 sAh[2][BM][24];
    __shared__ __nv_bfloat16 sAl[2][BM][24];
    __shared__ __nv_bfloat16 sBh[2][BK][136];
    __shared__ __nv_bfloat16 sBl[2][BK][136];

    const int tid  = threadIdx.x;
    const int lane = tid & 31;
    const int warp = tid >> 5;
    const int wm = warp >> 2;
    const int wn = warp & 3;
    const int row0 = blockIdx.y * BM;
    const int col0 = blockIdx.x * BN;
    const bool nAligned = ((N & 7) == 0);

    const int a_part = tid >> 7;
    const int a_m    = (tid & 127) >> 1;
    const int a_half = tid & 1;
    const int b_kr   = tid >> 4;
    const int b_ch   = tid & 15;

    float acc[2][4][4];
#pragma unroll
    for (int mt = 0; mt < 2; mt++)
#pragma unroll
        for (int nt = 0; nt < 4; nt++)
#pragma unroll
            for (int j = 0; j < 4; j++) acc[mt][nt][j] = 0.0f;

    const int NTILES = (K + BK - 1) / BK;

    auto stage = [&](int k0, int buf) {
        {
            const __nv_bfloat16* src = a_part ? Alo : Ahi;
            __nv_bfloat16* dst = a_part ? &sAl[buf][a_m][a_half * 8]
                                        : &sAh[buf][a_m][a_half * 8];
            int gr = row0 + a_m;
            int gk = k0 + a_half * 8;
            bool p = (gr < M) && (gk < K);
            cpa16(dst, src + (size_t)gr * K + gk, p);
        }
        {
            int gk = k0 + b_kr;
            int gn = col0 + b_ch * 8;
            if (nAligned) {
                bool p = (gk < K) && (gn < N);
                cpa16(&sBh[buf][b_kr][b_ch * 8], Bhi + (size_t)gk * N + gn, p);
                cpa16(&sBl[buf][b_kr][b_ch * 8], Blo + (size_t)gk * N + gn, p);
            } else {
#pragma unroll
                for (int j = 0; j < 8; j++) {
                    int c = gn + j;
                    bool p = (gk < K) && (c < N);
                    sBh[buf][b_kr][b_ch * 8 + j] = p ? Bhi[(size_t)gk * N + c] : __nv_bfloat16(0.0f);
                    sBl[buf][b_kr][b_ch * 8 + j] = p ? Blo[(size_t)gk * N + c] : __nv_bfloat16(0.0f);
                }
            }
        }
    };

    stage(0, 0);
    cp_commit();

    for (int it = 0; it < NTILES; ++it) {
        if (it + 1 < NTILES) stage((it + 1) * BK, (it + 1) & 1);
        cp_commit();
        cp_wait1();
        __syncthreads();

        const int buf = it & 1;
        uint32_t ah[2][4], al[2][4], bh[4][2], bl[4][2];
#pragma unroll
        for (int mt = 0; mt < 2; mt++) {
            int r = wm * 32 + mt * 16 + (lane & 15);
            int kk = (lane >> 4) * 8;
            ldsm_x4_p(ah[mt], &sAh[buf][r][kk]);
            ldsm_x4_p(al[mt], &sAl[buf][r][kk]);
        }
#pragma unroll
        for (int nt = 0; nt < 4; nt++) {
            int n0 = wn * 32 + nt * 8;
            int kr = lane & 15;
            ldsm_x2_t(bh[nt], &sBh[buf][kr][n0]);
            ldsm_x2_t(bl[nt], &sBl[buf][kr][n0]);
        }
#pragma unroll
        for (int mt = 0; mt < 2; mt++) {
#pragma unroll
            for (int nt = 0; nt < 4; nt++) {
                float* d = acc[mt][nt];
                mma_bf16(d[0], d[1], d[2], d[3], ah[mt], bh[nt]);
                mma_bf16(d[0], d[1], d[2], d[3], ah[mt], bl[nt]);
                mma_bf16(d[0], d[1], d[2], d[3], al[mt], bh[nt]);
            }
        }
        __syncthreads();
    }

#pragma unroll
    for (int mt = 0; mt < 2; mt++) {
#pragma unroll
        for (int nt = 0; nt < 4; nt++) {
            int rbase = row0 + wm * 32 + mt * 16 + (lane >> 2);
            int cbase = col0 + wn * 32 + nt * 8 + ((lane & 3) << 1);
#pragma unroll
            for (int half = 0; half < 2; half++) {
                int row = rbase + half * 8;
                if (row >= M) continue;
                int orow = row;
                if (REMAP) {
                    int bb = row % BSZ;
                    int tt = row / BSZ;
                    orow = bb * TSZ + tt;
                }
#pragma unroll
                for (int j = 0; j < 2; j++) {
                    int col = cbase + j;
                    if (col >= N) continue;
                    float v = acc[mt][nt][half * 2 + j];
                    if (bias) v += bias[col];
                    if (RELU) v = fmaxf(v, 0.0f);
                    size_t o = (size_t)orow * N + col;
                    if (WF32) Cf[o] = v;
                    if (WSPLIT) {
                        uint32_t uv = __float_as_uint(v);
                        float hf = __uint_as_float(uv & 0xFFFF0000u);
                        uint16_t hb = (uint16_t)(uv >> 16);
                        *reinterpret_cast<uint16_t*>(&Chi[o]) = hb;
                        Clo[o] = __float2bfloat16(v - hf);
                    }
                }
            }
        }
    }
}

// ---------------------------------------------------------------------------
// SRU recurrence (R10 structure; sigmoid via tanh -> 3 MUFU/elem)
// ---------------------------------------------------------------------------
__global__ __launch_bounds__(128)
void sru_scan_kernel(const float* __restrict__ U, const float* __restrict__ c0,
                     const float* __restrict__ sb, float* __restrict__ h,
                     __nv_bfloat16* __restrict__ Ahi, __nv_bfloat16* __restrict__ Alo,
                     float* __restrict__ c_out) {
    int idx = blockIdx.x * 128 + threadIdx.x;
    if (idx >= BSZ * HDIM) return;
    int hh = idx & (HDIM - 1);
    int b  = idx >> 10;
    float c  = c0[idx];
    float bf = sb[hh];
    float br = sb[HDIM + hh];
#pragma unroll
    for (int t0 = 0; t0 < TSZ; t0 += 5) {
        float xf[5], uf[5], ur[5], hv[5];
#pragma unroll
        for (int i = 0; i < 5; i++) {
            int row = (t0 + i) * BSZ + b;
            const float* Ur = U + (size_t)row * (3 * HDIM);
            xf[i] = Ur[hh];
            uf[i] = Ur[HDIM + hh];
            ur[i] = Ur[2 * HDIM + hh];
            hv[i] = h[(size_t)row * HDIM + hh];
        }
#pragma unroll
        for (int i = 0; i < 5; i++) {
            float f = sigmoid_fast(uf[i] + bf);
            float r = sigmoid_fast(ur[i] + br);
            c = f * c + (1.0f - f) * xf[i];
            float hn = r * tanh_fast(c) + (1.0f - r) * hv[i];
            size_t o = (size_t)((t0 + i) * BSZ + b) * HDIM + hh;
            h[o] = hn;
            uint32_t uv = __float_as_uint(hn);
            float hf = __uint_as_float(uv & 0xFFFF0000u);
            *reinterpret_cast<uint16_t*>(&Ahi[o]) = (uint16_t)(uv >> 16);
            Alo[o] = __float2bfloat16(hn - hf);
        }
    }
    c_out[idx] = c;
}

// ---------------------------------------------------------------------------
extern "C" void kernel_launch(void* const* d_in, const int* in_sizes, int n_in,
                              void* d_out, int out_size) {
    const float* x      = (const float*)d_in[0];
    const float* hidden = (const float*)d_in[1];
    const float* W1     = (const float*)d_in[2];
    const float* b1     = (const float*)d_in[3];
    const float* sru_W  = (const float*)d_in[4];
    const float* sru_b  = (const float*)d_in[5];
    const float* W3     = (const float*)d_in[6];
    const float* b3     = (const float*)d_in[7];
    const float* W4     = (const float*)d_in[8];
    const float* b4     = (const float*)d_in[9];
    float* out = (float*)d_out;

    float *h, *U;
    __nv_bfloat16 *xthi, *xtlo, *Ahi, *Alo, *A2hi, *A2lo, *Wsmhi, *Wsmlo, *Wshi, *Wslo;
    cudaGetSymbolAddress((void**)&h,    g_h);
    cudaGetSymbolAddress((void**)&U,    g_U);
    cudaGetSymbolAddress((void**)&xthi, g_xthi);
    cudaGetSymbolAddress((void**)&xtlo, g_xtlo);
    cudaGetSymbolAddress((void**)&Ahi,  g_Ahi);
    cudaGetSymbolAddress((void**)&Alo,  g_Alo);
    cudaGetSymbolAddress((void**)&A2hi, g_A2hi);
    cudaGetSymbolAddress((void**)&A2lo, g_A2lo);
    cudaGetSymbolAddress((void**)&Wsmhi, g_Wsmhi);
    cudaGetSymbolAddress((void**)&Wsmlo, g_Wsmlo);
    cudaGetSymbolAddress((void**)&Wshi, g_Wshi);
    cudaGetSymbolAddress((void**)&Wslo, g_Wslo);

    static bool attr_set = false;
    if (!attr_set) {
        cudaFuncSetAttribute(u_gemm_kernel,
                             cudaFuncAttributeMaxDynamicSharedMemorySize, U_SM_TOTAL);
        attr_set = true;
    }

    // Preprocessing (per-call; deterministic)
    transpose_split_kernel<<<(MROWS * FEAD + 255) / 256, 256>>>(x, xthi, xtlo);
    split8_kernel<<<(N_W1 / 8 + 255) / 256, 256>>>((const float4*)W1, (uint4*)(Wsmhi + OFF_W1), (uint4*)(Wsmlo + OFF_W1), N_W1 / 8);
    split8_kernel<<<(N_W3 / 8 + 255) / 256, 256>>>((const float4*)W3, (uint4*)(Wsmhi + OFF_W3), (uint4*)(Wsmlo + OFF_W3), N_W3 / 8);
    split8_kernel<<<(N_W4 / 8 + 255) / 256, 256>>>((const float4*)W4, (uint4*)(Wsmhi + OFF_W4), (uint4*)(Wsmlo + OFF_W4), N_W4 / 8);
    split8_kernel<<<(N_SRU / 8 + 255) / 256, 256>>>((const float4*)sru_W, (uint4*)Wshi, (uint4*)Wslo, N_SRU / 8);
    zeropad_kernel<<<((MPAD - MROWS) * HDIM / 2 + 255) / 256, 256>>>(Ahi, Alo);

    const int GY = (MROWS + BM - 1) / BM;

    // Dense layer 1
    {
        dim3 grid((HDIM + BN - 1) / BN, GY);
        mma_gemm<0, 0, 1, 1><<<grid, 256>>>(xthi, xtlo, Wsmhi + OFF_W1, Wsmlo + OFF_W1,
                                            b1, h, Ahi, Alo, MROWS, FEAD, HDIM);
    }

    // SRU layers
    for (int l = 0; l < LNUM; l++) {
        size_t woff = (size_t)l * HDIM * 3 * HDIM;
        dim3 gridU(UN / UBN, MPAD / UBM);   // 16 x 7
        u_gemm_kernel<<<gridU, 384, U_SM_TOTAL>>>(Ahi, Alo, Wshi + woff, Wslo + woff, U);
        sru_scan_kernel<<<(BSZ * HDIM + 127) / 128, 128>>>(
            U, hidden + (size_t)l * BSZ * HDIM, sru_b + (size_t)l * 2 * HDIM,
            h, Ahi, Alo, out + OUT_ELEMS + (size_t)l * BSZ * HDIM);
    }

    // Dense ReLU with row remap
    {
        dim3 grid((HDIM + BN - 1) / BN, GY);
        mma_gemm<1, 1, 0, 1><<<grid, 256>>>(Ahi, Alo, Wsmhi + OFF_W3, Wsmlo + OFF_W3,
                                            b3, nullptr, A2hi, A2lo, MROWS, HDIM, HDIM);
    }

    // Output projection
    {
        dim3 grid((OUTD + BN - 1) / BN, GY);
        mma_gemm<0, 0, 1, 0><<<grid, 256>>>(A2hi, A2lo, Wsmhi + OFF_W4, Wsmlo + OFF_W4,
                                            b4, out, nullptr, nullptr, MROWS, HDIM, OUTD);
    }
}

// round 16
// speedup vs baseline: 2.0655x; 1.2597x over previous
#include <cuda_runtime.h>
#include <cuda_bf16.h>
#include <cstdint>
#include <cstddef>

#define BSZ   40
#define TSZ   20
#define FEAD  200
#define HDIM  1024
#define OUTD  1095
#define LNUM  12
#define MROWS (BSZ * TSZ)          // 800
#define MPAD  896                  // 7 * 128
#define OUT_ELEMS (MROWS * OUTD)   // 876000

#define OFF_W1  0
#define N_W1    (FEAD * HDIM)
#define OFF_W3  (OFF_W1 + N_W1)
#define N_W3    (HDIM * HDIM)
#define OFF_W4  (OFF_W3 + N_W3)
#define N_W4    (HDIM * OUTD)
#define N_WSM   (OFF_W4 + N_W4)

// ---------------------------------------------------------------------------
// Scratch
// ---------------------------------------------------------------------------
__device__ __align__(16) float g_h [MPAD * HDIM];      // padded for tf32 U-GEMM
__device__ __align__(16) float g_U [MROWS * 3 * HDIM];
__device__ __align__(16) __nv_bfloat16 g_xthi[MROWS * FEAD];
__device__ __align__(16) __nv_bfloat16 g_xtlo[MROWS * FEAD];
__device__ __align__(16) __nv_bfloat16 g_Ahi [MROWS * HDIM];
__device__ __align__(16) __nv_bfloat16 g_Alo [MROWS * HDIM];
__device__ __align__(16) __nv_bfloat16 g_A2hi[MROWS * HDIM];
__device__ __align__(16) __nv_bfloat16 g_A2lo[MROWS * HDIM];
__device__ __align__(16) __nv_bfloat16 g_Wsmhi[N_WSM];
__device__ __align__(16) __nv_bfloat16 g_Wsmlo[N_WSM];

// ---------------------------------------------------------------------------
// PTX helpers
// ---------------------------------------------------------------------------
__device__ __forceinline__ void cpa16(void* dst, const void* src, bool pred) {
    unsigned d = (unsigned)__cvta_generic_to_shared(dst);
    if (pred) {
        asm volatile("cp.async.cg.shared.global [%0], [%1], 16;\n" :: "r"(d), "l"(src) : "memory");
    } else {
        uint4 z = {0u, 0u, 0u, 0u};
        *reinterpret_cast<uint4*>(dst) = z;
    }
}
__device__ __forceinline__ void cpa16s(uint32_t daddr, const void* src) {
    asm volatile("cp.async.cg.shared.global [%0], [%1], 16;\n" :: "r"(daddr), "l"(src) : "memory");
}
__device__ __forceinline__ void cp_commit() { asm volatile("cp.async.commit_group;\n" ::: "memory"); }
__device__ __forceinline__ void cp_wait1()  { asm volatile("cp.async.wait_group 1;\n" ::: "memory"); }
__device__ __forceinline__ void cp_wait0()  { asm volatile("cp.async.wait_group 0;\n" ::: "memory"); }

__device__ __forceinline__ void ldsm_x4_p(uint32_t* r, const void* p) {
    unsigned a = (unsigned)__cvta_generic_to_shared(p);
    asm volatile("ldmatrix.sync.aligned.m8n8.x4.shared.b16 {%0,%1,%2,%3}, [%4];\n"
                 : "=r"(r[0]), "=r"(r[1]), "=r"(r[2]), "=r"(r[3]) : "r"(a));
}
__device__ __forceinline__ void ldsm_x2_t(uint32_t* r, const void* p) {
    unsigned a = (unsigned)__cvta_generic_to_shared(p);
    asm volatile("ldmatrix.sync.aligned.m8n8.x2.trans.shared.b16 {%0,%1}, [%2];\n"
                 : "=r"(r[0]), "=r"(r[1]) : "r"(a));
}
__device__ __forceinline__ void mma_bf16(float& d0, float& d1, float& d2, float& d3,
                                         const uint32_t a[4], const uint32_t b[2]) {
    asm volatile("mma.sync.aligned.m16n8k16.row.col.f32.bf16.bf16.f32 "
                 "{%0,%1,%2,%3}, {%4,%5,%6,%7}, {%8,%9}, {%0,%1,%2,%3};\n"
                 : "+f"(d0), "+f"(d1), "+f"(d2), "+f"(d3)
                 : "r"(a[0]), "r"(a[1]), "r"(a[2]), "r"(a[3]), "r"(b[0]), "r"(b[1]));
}
__device__ __forceinline__ void mma_tf32(float& d0, float& d1, float& d2, float& d3,
                                         const uint32_t a[4], const uint32_t b[2]) {
    asm volatile("mma.sync.aligned.m16n8k8.row.col.f32.tf32.tf32.f32 "
                 "{%0,%1,%2,%3}, {%4,%5,%6,%7}, {%8,%9}, {%0,%1,%2,%3};\n"
                 : "+f"(d0), "+f"(d1), "+f"(d2), "+f"(d3)
                 : "r"(a[0]), "r"(a[1]), "r"(a[2]), "r"(a[3]), "r"(b[0]), "r"(b[1]));
}
__device__ __forceinline__ uint32_t f2tf(float x) {
    uint32_t r; asm("cvt.rna.tf32.f32 %0, %1;" : "=r"(r) : "f"(x)); return r;
}
__device__ __forceinline__ float tanh_fast(float x) {
    float y; asm("tanh.approx.f32 %0, %1;" : "=f"(y) : "f"(x)); return y;
}
__device__ __forceinline__ float sigmoid_fast(float x) {
    return 0.5f + 0.5f * tanh_fast(0.5f * x);
}
// truncation hi + RN lo pair split (packed bf16x2)
__device__ __forceinline__ void split2(float a, float b, uint32_t& h, uint32_t& l) {
    uint32_t ua = __float_as_uint(a);
    uint32_t ub = __float_as_uint(b);
    h = __byte_perm(ua, ub, 0x7632);
    float ha = __uint_as_float(ua & 0xFFFF0000u);
    float hb = __uint_as_float(ub & 0xFFFF0000u);
    float la = a - ha;
    float lb = b - hb;
    asm("cvt.rn.bf16x2.f32 %0, %1, %2;" : "=r"(l) : "f"(lb), "f"(la));
}

// ---------------------------------------------------------------------------
// Preprocessing
// ---------------------------------------------------------------------------
__global__ void split8_kernel(const float4* __restrict__ src,
                              uint4* __restrict__ hi, uint4* __restrict__ lo, int n8) {
    int i = blockIdx.x * blockDim.x + threadIdx.x;
    if (i >= n8) return;
    float4 a = src[2 * i];
    float4 b = src[2 * i + 1];
    uint4 H, L;
    split2(a.x, a.y, H.x, L.x);
    split2(a.z, a.w, H.y, L.y);
    split2(b.x, b.y, H.z, L.z);
    split2(b.z, b.w, H.w, L.w);
    hi[i] = H;
    lo[i] = L;
}

__global__ void transpose_split_kernel(const float* __restrict__ x,
                                       __nv_bfloat16* __restrict__ hi,
                                       __nv_bfloat16* __restrict__ lo) {
    int idx = blockIdx.x * blockDim.x + threadIdx.x;
    if (idx >= MROWS * FEAD) return;
    int f = idx % FEAD;
    int m = idx / FEAD;
    int b = m % BSZ;
    int t = m / BSZ;
    float v = x[((size_t)b * TSZ + t) * FEAD + f];
    uint32_t uv = __float_as_uint(v);
    float hf = __uint_as_float(uv & 0xFFFF0000u);
    __nv_bfloat16 hb;
    *reinterpret_cast<uint16_t*>(&hb) = (uint16_t)(uv >> 16);
    hi[idx] = hb;
    lo[idx] = __float2bfloat16(v - hf);
}

// zero rows [800, 896) of g_h (fp32)
__global__ void zeropad_h_kernel(float* __restrict__ h) {
    int i = blockIdx.x * blockDim.x + threadIdx.x;
    int n = (MPAD - MROWS) * HDIM;
    if (i >= n) return;
    h[(size_t)MROWS * HDIM + i] = 0.0f;
}

// ---------------------------------------------------------------------------
// tf32 U-GEMM: U[800,3072] = h[.,1024] @ sru_W[1024,3072]
// Raw fp32 operands, cp.async double-buffered, in-register cvt.rna.tf32.
// BM=128, BN=192, BK=32, 384 threads (4x3 warps, 32x64 warp tile).
// ---------------------------------------------------------------------------
#define UK   1024
#define UN   3072
#define UBM  128
#define UBN  192
#define UBK  32
#define UNIT (UK / UBK)            // 32
#define UASTR 36                   // A row stride (floats): banks 4g+t, bijective
#define UBSTR 200                  // B row stride (floats): banks 8k+n, bijective
#define UA_PB (UBM * UASTR * 4)    // 18432 B
#define UB_PB (UBK * UBSTR * 4)    // 25600 B
#define U_SM_A 0
#define U_SM_B (2 * UA_PB)         // 36864
#define U_SM_TOTAL (U_SM_B + 2 * UB_PB)   // 88064

__global__ __launch_bounds__(384, 1)
void u_gemm_kernel(const float* __restrict__ A,
                   const float* __restrict__ Bf,
                   float* __restrict__ U) {
    extern __shared__ char dsm[];
    uint32_t smem;
    asm("{ .reg .u64 t; cvta.to.shared.u64 t, %1; cvt.u32.u64 %0, t; }"
        : "=r"(smem) : "l"(dsm));

    const int tid  = threadIdx.x;
    const int warp = tid >> 5;
    const int lane = tid & 31;
    const int wrow = warp / 3;         // 0..3
    const int wcol = warp % 3;         // 0..2
    const int row0 = blockIdx.y * UBM;
    const int col0 = blockIdx.x * UBN;
    const int lg = lane >> 2;          // 0..7
    const int lt = lane & 3;           // 0..3

    float acc[2][8][4];
#pragma unroll
    for (int a = 0; a < 2; a++)
#pragma unroll
        for (int b = 0; b < 8; b++)
#pragma unroll
            for (int c = 0; c < 4; c++) acc[a][b][c] = 0.0f;

    auto stage = [&](int it, int buf) {
        const int k0 = it * UBK;
        // A: 128 rows x 8 float4-chunks = 1024
#pragma unroll
        for (int i = 0; i < 3; i++) {
            int idx = tid + i * 384;
            if (idx < 1024) {
                int r = idx >> 3, kc = idx & 7;
                uint32_t daddr = smem + U_SM_A + buf * UA_PB + r * (UASTR * 4) + kc * 16;
                cpa16s(daddr, A + (size_t)(row0 + r) * UK + k0 + kc * 4);
            }
        }
        // B: 32 rows x 48 float4-chunks = 1536
#pragma unroll
        for (int i = 0; i < 4; i++) {
            int c = tid + i * 384;
            int r = c / 48, f4 = c % 48;
            uint32_t daddr = smem + U_SM_B + buf * UB_PB + r * (UBSTR * 4) + f4 * 16;
            cpa16s(daddr, Bf + (size_t)(k0 + r) * UN + col0 + f4 * 4);
        }
    };

    stage(0, 0);
    cp_commit();

    for (int it = 0; it < UNIT; ++it) {
        if (it + 1 < UNIT) {
            stage(it + 1, (it + 1) & 1);
            cp_commit();
            cp_wait1();
        } else {
            cp_wait0();
        }
        __syncthreads();
        const int buf = it & 1;
        const float* fA = (const float*)(dsm + U_SM_A + buf * UA_PB);
        const float* fB = (const float*)(dsm + U_SM_B + buf * UB_PB);

#pragma unroll
        for (int kk = 0; kk < 4; kk++) {            // 4 x k8
            uint32_t af[2][4];
#pragma unroll
            for (int mt = 0; mt < 2; mt++) {
                int rb = wrow * 32 + mt * 16 + lg;
                int cb = kk * 8 + lt;
                af[mt][0] = f2tf(fA[rb * UASTR + cb]);
                af[mt][1] = f2tf(fA[(rb + 8) * UASTR + cb]);
                af[mt][2] = f2tf(fA[rb * UASTR + cb + 4]);
                af[mt][3] = f2tf(fA[(rb + 8) * UASTR + cb + 4]);
            }
            uint32_t bf2[8][2];
#pragma unroll
            for (int nt = 0; nt < 8; nt++) {
                int n = wcol * 64 + nt * 8 + lg;
                int k = kk * 8 + lt;
                bf2[nt][0] = f2tf(fB[k * UBSTR + n]);
                bf2[nt][1] = f2tf(fB[(k + 4) * UBSTR + n]);
            }
#pragma unroll
            for (int mt = 0; mt < 2; mt++)
#pragma unroll
                for (int nt = 0; nt < 8; nt++) {
                    float* d = acc[mt][nt];
                    mma_tf32(d[0], d[1], d[2], d[3], af[mt], bf2[nt]);
                }
        }
        __syncthreads();
    }

    // Epilogue
#pragma unroll
    for (int mt = 0; mt < 2; mt++) {
#pragma unroll
        for (int half = 0; half < 2; half++) {
            int row = row0 + wrow * 32 + mt * 16 + lg + half * 8;
            if (row >= MROWS) continue;
            float* dst = U + (size_t)row * UN;
#pragma unroll
            for (int nt = 0; nt < 8; nt++) {
                int col = col0 + wcol * 64 + nt * 8 + lt * 2;
                float2 v;
                v.x = acc[mt][nt][half * 2 + 0];
                v.y = acc[mt][nt][half * 2 + 1];
                *reinterpret_cast<float2*>(dst + col) = v;
            }
        }
    }
}

// ---------------------------------------------------------------------------
// Dense GEMM (bf16x3, pre-split weights — unchanged from R15)
// ---------------------------------------------------------------------------
#define BM 64
#define BN 128
#define BK 16

template<int RELU, int REMAP, int WF32, int WSPLIT>
__global__ __launch_bounds__(256, 2)
void mma_gemm(const __nv_bfloat16* __restrict__ Ahi, const __nv_bfloat16* __restrict__ Alo,
              const __nv_bfloat16* __restrict__ Bhi, const __nv_bfloat16* __restrict__ Blo,
              const float* __restrict__ bias,
              float* __restrict__ Cf,
              __nv_bfloat16* __restrict__ Chi, __nv_bfloat16* __restrict__ Clo,
              int M, int K, int N) {
    __shared__ __nv_bfloat16 sAh[2][BM][24];
    __shared__ __nv_bfloat16 sAl[2][BM][24];
    __shared__ __nv_bfloat16 sBh[2][BK][136];
    __shared__ __nv_bfloat16 sBl[2][BK][136];

    const int tid  = threadIdx.x;
    const int lane = tid & 31;
    const int warp = tid >> 5;
    const int wm = warp >> 2;
    const int wn = warp & 3;
    const int row0 = blockIdx.y * BM;
    const int col0 = blockIdx.x * BN;
    const bool nAligned = ((N & 7) == 0);

    const int a_part = tid >> 7;
    const int a_m    = (tid & 127) >> 1;
    const int a_half = tid & 1;
    const int b_kr   = tid >> 4;
    const int b_ch   = tid & 15;

    float acc[2][4][4];
#pragma unroll
    for (int mt = 0; mt < 2; mt++)
#pragma unroll
        for (int nt = 0; nt < 4; nt++)
#pragma unroll
            for (int j = 0; j < 4; j++) acc[mt][nt][j] = 0.0f;

    const int NTILES = (K + BK - 1) / BK;

    auto stage = [&](int k0, int buf) {
        {
            const __nv_bfloat16* src = a_part ? Alo : Ahi;
            __nv_bfloat16* dst = a_part ? &sAl[buf][a_m][a_half * 8]
                                        : &sAh[buf][a_m][a_half * 8];
            int gr = row0 + a_m;
            int gk = k0 + a_half * 8;
            bool p = (gr < M) && (gk < K);
            cpa16(dst, src + (size_t)gr * K + gk, p);
        }
        {
            int gk = k0 + b_kr;
            int gn = col0 + b_ch * 8;
            if (nAligned) {
                bool p = (gk < K) && (gn < N);
                cpa16(&sBh[buf][b_kr][b_ch * 8], Bhi + (size_t)gk * N + gn, p);
                cpa16(&sBl[buf][b_kr][b_ch * 8], Blo + (size_t)gk * N + gn, p);
            } else {
#pragma unroll
                for (int j = 0; j < 8; j++) {
                    int c = gn + j;
                    bool p = (gk < K) && (c < N);
                    sBh[buf][b_kr][b_ch * 8 + j] = p ? Bhi[(size_t)gk * N + c] : __nv_bfloat16(0.0f);
                    sBl[buf][b_kr][b_ch * 8 + j] = p ? Blo[(size_t)gk * N + c] : __nv_bfloat16(0.0f);
                }
            }
        }
    };

    stage(0, 0);
    cp_commit();

    for (int it = 0; it < NTILES; ++it) {
        if (it + 1 < NTILES) stage((it + 1) * BK, (it + 1) & 1);
        cp_commit();
        cp_wait1();
        __syncthreads();

        const int buf = it & 1;
        uint32_t ah[2][4], al[2][4], bh[4][2], bl[4][2];
#pragma unroll
        for (int mt = 0; mt < 2; mt++) {
            int r = wm * 32 + mt * 16 + (lane & 15);
            int kk = (lane >> 4) * 8;
            ldsm_x4_p(ah[mt], &sAh[buf][r][kk]);
            ldsm_x4_p(al[mt], &sAl[buf][r][kk]);
        }
#pragma unroll
        for (int nt = 0; nt < 4; nt++) {
            int n0 = wn * 32 + nt * 8;
            int kr = lane & 15;
            ldsm_x2_t(bh[nt], &sBh[buf][kr][n0]);
            ldsm_x2_t(bl[nt], &sBl[buf][kr][n0]);
        }
#pragma unroll
        for (int mt = 0; mt < 2; mt++) {
#pragma unroll
            for (int nt = 0; nt < 4; nt++) {
                float* d = acc[mt][nt];
                mma_bf16(d[0], d[1], d[2], d[3], ah[mt], bh[nt]);
                mma_bf16(d[0], d[1], d[2], d[3], ah[mt], bl[nt]);
                mma_bf16(d[0], d[1], d[2], d[3], al[mt], bh[nt]);
            }
        }
        __syncthreads();
    }

#pragma unroll
    for (int mt = 0; mt < 2; mt++) {
#pragma unroll
        for (int nt = 0; nt < 4; nt++) {
            int rbase = row0 + wm * 32 + mt * 16 + (lane >> 2);
            int cbase = col0 + wn * 32 + nt * 8 + ((lane & 3) << 1);
#pragma unroll
            for (int half = 0; half < 2; half++) {
                int row = rbase + half * 8;
                if (row >= M) continue;
                int orow = row;
                if (REMAP) {
                    int bb = row % BSZ;
                    int tt = row / BSZ;
                    orow = bb * TSZ + tt;
                }
#pragma unroll
                for (int j = 0; j < 2; j++) {
                    int col = cbase + j;
                    if (col >= N) continue;
                    float v = acc[mt][nt][half * 2 + j];
                    if (bias) v += bias[col];
                    if (RELU) v = fmaxf(v, 0.0f);
                    size_t o = (size_t)orow * N + col;
                    if (WF32) Cf[o] = v;
                    if (WSPLIT) {
                        uint32_t uv = __float_as_uint(v);
                        float hf = __uint_as_float(uv & 0xFFFF0000u);
                        *reinterpret_cast<uint16_t*>(&Chi[o]) = (uint16_t)(uv >> 16);
                        Clo[o] = __float2bfloat16(v - hf);
                    }
                }
            }
        }
    }
}

// ---------------------------------------------------------------------------
// SRU recurrence (R15 version)
// ---------------------------------------------------------------------------
__global__ __launch_bounds__(128)
void sru_scan_kernel(const float* __restrict__ U, const float* __restrict__ c0,
                     const float* __restrict__ sb, float* __restrict__ h,
                     __nv_bfloat16* __restrict__ Ahi, __nv_bfloat16* __restrict__ Alo,
                     float* __restrict__ c_out) {
    int idx = blockIdx.x * 128 + threadIdx.x;
    if (idx >= BSZ * HDIM) return;
    int hh = idx & (HDIM - 1);
    int b  = idx >> 10;
    float c  = c0[idx];
    float bf = sb[hh];
    float br = sb[HDIM + hh];
#pragma unroll
    for (int t0 = 0; t0 < TSZ; t0 += 5) {
        float xf[5], uf[5], ur[5], hv[5];
#pragma unroll
        for (int i = 0; i < 5; i++) {
            int row = (t0 + i) * BSZ + b;
            const float* Ur = U + (size_t)row * (3 * HDIM);
            xf[i] = Ur[hh];
            uf[i] = Ur[HDIM + hh];
            ur[i] = Ur[2 * HDIM + hh];
            hv[i] = h[(size_t)row * HDIM + hh];
        }
#pragma unroll
        for (int i = 0; i < 5; i++) {
            float f = sigmoid_fast(uf[i] + bf);
            float r = sigmoid_fast(ur[i] + br);
            c = f * c + (1.0f - f) * xf[i];
            float hn = r * tanh_fast(c) + (1.0f - r) * hv[i];
            size_t o = (size_t)((t0 + i) * BSZ + b) * HDIM + hh;
            h[o] = hn;
            uint32_t uv = __float_as_uint(hn);
            float hf = __uint_as_float(uv & 0xFFFF0000u);
            *reinterpret_cast<uint16_t*>(&Ahi[o]) = (uint16_t)(uv >> 16);
            Alo[o] = __float2bfloat16(hn - hf);
        }
    }
    c_out[idx] = c;
}

// ---------------------------------------------------------------------------
extern "C" void kernel_launch(void* const* d_in, const int* in_sizes, int n_in,
                              void* d_out, int out_size) {
    const float* x      = (const float*)d_in[0];
    const float* hidden = (const float*)d_in[1];
    const float* W1     = (const float*)d_in[2];
    const float* b1     = (const float*)d_in[3];
    const float* sru_W  = (const float*)d_in[4];
    const float* sru_b  = (const float*)d_in[5];
    const float* W3     = (const float*)d_in[6];
    const float* b3     = (const float*)d_in[7];
    const float* W4     = (const float*)d_in[8];
    const float* b4     = (const float*)d_in[9];
    float* out = (float*)d_out;

    float *h, *U;
    __nv_bfloat16 *xthi, *xtlo, *Ahi, *Alo, *A2hi, *A2lo, *Wsmhi, *Wsmlo;
    cudaGetSymbolAddress((void**)&h,    g_h);
    cudaGetSymbolAddress((void**)&U,    g_U);
    cudaGetSymbolAddress((void**)&xthi, g_xthi);
    cudaGetSymbolAddress((void**)&xtlo, g_xtlo);
    cudaGetSymbolAddress((void**)&Ahi,  g_Ahi);
    cudaGetSymbolAddress((void**)&Alo,  g_Alo);
    cudaGetSymbolAddress((void**)&A2hi, g_A2hi);
    cudaGetSymbolAddress((void**)&A2lo, g_A2lo);
    cudaGetSymbolAddress((void**)&Wsmhi, g_Wsmhi);
    cudaGetSymbolAddress((void**)&Wsmlo, g_Wsmlo);

    static bool attr_set = false;
    if (!attr_set) {
        cudaFuncSetAttribute(u_gemm_kernel,
                             cudaFuncAttributeMaxDynamicSharedMemorySize, U_SM_TOTAL);
        attr_set = true;
    }

    // Preprocessing: small weights + input transpose + fp32 row padding
    transpose_split_kernel<<<(MROWS * FEAD + 255) / 256, 256>>>(x, xthi, xtlo);
    split8_kernel<<<(N_W1 / 8 + 255) / 256, 256>>>((const float4*)W1, (uint4*)(Wsmhi + OFF_W1), (uint4*)(Wsmlo + OFF_W1), N_W1 / 8);
    split8_kernel<<<(N_W3 / 8 + 255) / 256, 256>>>((const float4*)W3, (uint4*)(Wsmhi + OFF_W3), (uint4*)(Wsmlo + OFF_W3), N_W3 / 8);
    split8_kernel<<<(N_W4 / 8 + 255) / 256, 256>>>((const float4*)W4, (uint4*)(Wsmhi + OFF_W4), (uint4*)(Wsmlo + OFF_W4), N_W4 / 8);
    zeropad_h_kernel<<<((MPAD - MROWS) * HDIM + 255) / 256, 256>>>(h);

    const int GY = (MROWS + BM - 1) / BM;

    // Dense layer 1: h = xt @ W1 + b1 (fp32 only; U-GEMM reads fp32 h directly)
    {
        dim3 grid((HDIM + BN - 1) / BN, GY);
        mma_gemm<0, 0, 1, 0><<<grid, 256>>>(xthi, xtlo, Wsmhi + OFF_W1, Wsmlo + OFF_W1,
                                            b1, h, nullptr, nullptr, MROWS, FEAD, HDIM);
    }

    // SRU layers: tf32 U-GEMM (raw sru_W!) + scan
    for (int l = 0; l < LNUM; l++) {
        dim3 gridU(UN / UBN, MPAD / UBM);   // 16 x 7 = 112 blocks
        u_gemm_kernel<<<gridU, 384, U_SM_TOTAL>>>(h, sru_W + (size_t)l * HDIM * 3 * HDIM, U);
        sru_scan_kernel<<<(BSZ * HDIM + 127) / 128, 128>>>(
            U, hidden + (size_t)l * BSZ * HDIM, sru_b + (size_t)l * 2 * HDIM,
            h, Ahi, Alo, out + OUT_ELEMS + (size_t)l * BSZ * HDIM);
    }

    // Dense ReLU with row remap (input: bf16 split written by last scan)
    {
        dim3 grid((HDIM + BN - 1) / BN, GY);
        mma_gemm<1, 1, 0, 1><<<grid, 256>>>(Ahi, Alo, Wsmhi + OFF_W3, Wsmlo + OFF_W3,
                                            b3, nullptr, A2hi, A2lo, MROWS, HDIM, HDIM);
    }

    // Output projection
    {
        dim3 grid((OUTD + BN - 1) / BN, GY);
        mma_gemm<0, 0, 1, 0><<<grid, 256>>>(A2hi, A2lo, Wsmhi + OFF_W4, Wsmlo + OFF_W4,
                                            b4, out, nullptr, nullptr, MROWS, HDIM, OUTD);
    }
}

// round 17
// speedup vs baseline: 2.0866x; 1.0103x over previous
#include <cuda_runtime.h>
#include <cuda_bf16.h>
#include <cstdint>
#include <cstddef>

#define BSZ   40
#define TSZ   20
#define FEAD  200
#define HDIM  1024
#define OUTD  1095
#define LNUM  12
#define MROWS (BSZ * TSZ)          // 800
#define OUT_ELEMS (MROWS * OUTD)   // 876000

#define OFF_W1  0
#define N_W1    (FEAD * HDIM)
#define OFF_W3  (OFF_W1 + N_W1)
#define N_W3    (HDIM * HDIM)
#define OFF_W4  (OFF_W3 + N_W3)
#define N_W4    (HDIM * OUTD)
#define N_WSM   (OFF_W4 + N_W4)

// ---------------------------------------------------------------------------
// Scratch
// ---------------------------------------------------------------------------
__device__ __align__(16) float g_h [MROWS * HDIM];
__device__ __align__(16) float g_U [MROWS * 3 * HDIM];
__device__ __align__(16) __nv_bfloat16 g_xthi[MROWS * FEAD];
__device__ __align__(16) __nv_bfloat16 g_xtlo[MROWS * FEAD];
__device__ __align__(16) __nv_bfloat16 g_Ahi [MROWS * HDIM];
__device__ __align__(16) __nv_bfloat16 g_Alo [MROWS * HDIM];
__device__ __align__(16) __nv_bfloat16 g_A2hi[MROWS * HDIM];
__device__ __align__(16) __nv_bfloat16 g_A2lo[MROWS * HDIM];
__device__ __align__(16) __nv_bfloat16 g_Wsmhi[N_WSM];
__device__ __align__(16) __nv_bfloat16 g_Wsmlo[N_WSM];

// ---------------------------------------------------------------------------
// PTX helpers
// ---------------------------------------------------------------------------
__device__ __forceinline__ void cpa16(void* dst, const void* src, bool pred) {
    unsigned d = (unsigned)__cvta_generic_to_shared(dst);
    if (pred) {
        asm volatile("cp.async.cg.shared.global [%0], [%1], 16;\n" :: "r"(d), "l"(src) : "memory");
    } else {
        uint4 z = {0u, 0u, 0u, 0u};
        *reinterpret_cast<uint4*>(dst) = z;
    }
}
__device__ __forceinline__ void cpa16s(uint32_t daddr, const void* src) {
    asm volatile("cp.async.cg.shared.global [%0], [%1], 16;\n" :: "r"(daddr), "l"(src) : "memory");
}
__device__ __forceinline__ void cp_commit() { asm volatile("cp.async.commit_group;\n" ::: "memory"); }
__device__ __forceinline__ void cp_wait1()  { asm volatile("cp.async.wait_group 1;\n" ::: "memory"); }
__device__ __forceinline__ void cp_wait0()  { asm volatile("cp.async.wait_group 0;\n" ::: "memory"); }

__device__ __forceinline__ void ldsm_x4_p(uint32_t* r, const void* p) {
    unsigned a = (unsigned)__cvta_generic_to_shared(p);
    asm volatile("ldmatrix.sync.aligned.m8n8.x4.shared.b16 {%0,%1,%2,%3}, [%4];\n"
                 : "=r"(r[0]), "=r"(r[1]), "=r"(r[2]), "=r"(r[3]) : "r"(a));
}
__device__ __forceinline__ void ldsm_x2_t(uint32_t* r, const void* p) {
    unsigned a = (unsigned)__cvta_generic_to_shared(p);
    asm volatile("ldmatrix.sync.aligned.m8n8.x2.trans.shared.b16 {%0,%1}, [%2];\n"
                 : "=r"(r[0]), "=r"(r[1]) : "r"(a));
}
__device__ __forceinline__ void mma_bf16(float& d0, float& d1, float& d2, float& d3,
                                         const uint32_t a[4], const uint32_t b[2]) {
    asm volatile("mma.sync.aligned.m16n8k16.row.col.f32.bf16.bf16.f32 "
                 "{%0,%1,%2,%3}, {%4,%5,%6,%7}, {%8,%9}, {%0,%1,%2,%3};\n"
                 : "+f"(d0), "+f"(d1), "+f"(d2), "+f"(d3)
                 : "r"(a[0]), "r"(a[1]), "r"(a[2]), "r"(a[3]), "r"(b[0]), "r"(b[1]));
}
__device__ __forceinline__ void mma_tf32(float& d0, float& d1, float& d2, float& d3,
                                         const uint32_t a[4], const uint32_t b[2]) {
    asm volatile("mma.sync.aligned.m16n8k8.row.col.f32.tf32.tf32.f32 "
                 "{%0,%1,%2,%3}, {%4,%5,%6,%7}, {%8,%9}, {%0,%1,%2,%3};\n"
                 : "+f"(d0), "+f"(d1), "+f"(d2), "+f"(d3)
                 : "r"(a[0]), "r"(a[1]), "r"(a[2]), "r"(a[3]), "r"(b[0]), "r"(b[1]));
}
__device__ __forceinline__ uint32_t f2tf(float x) {
    uint32_t r; asm("cvt.rna.tf32.f32 %0, %1;" : "=r"(r) : "f"(x)); return r;
}
__device__ __forceinline__ float tanh_fast(float x) {
    float y; asm("tanh.approx.f32 %0, %1;" : "=f"(y) : "f"(x)); return y;
}
__device__ __forceinline__ float sigmoid_fast(float x) {
    return 0.5f + 0.5f * tanh_fast(0.5f * x);
}
__device__ __forceinline__ void split2(float a, float b, uint32_t& h, uint32_t& l) {
    uint32_t ua = __float_as_uint(a);
    uint32_t ub = __float_as_uint(b);
    h = __byte_perm(ua, ub, 0x7632);
    float ha = __uint_as_float(ua & 0xFFFF0000u);
    float hb = __uint_as_float(ub & 0xFFFF0000u);
    float la = a - ha;
    float lb = b - hb;
    asm("cvt.rn.bf16x2.f32 %0, %1, %2;" : "=r"(l) : "f"(lb), "f"(la));
}

// ---------------------------------------------------------------------------
// Preprocessing
// ---------------------------------------------------------------------------
__global__ void split8_kernel(const float4* __restrict__ src,
                              uint4* __restrict__ hi, uint4* __restrict__ lo, int n8) {
    int i = blockIdx.x * blockDim.x + threadIdx.x;
    if (i >= n8) return;
    float4 a = src[2 * i];
    float4 b = src[2 * i + 1];
    uint4 H, L;
    split2(a.x, a.y, H.x, L.x);
    split2(a.z, a.w, H.y, L.y);
    split2(b.x, b.y, H.z, L.z);
    split2(b.z, b.w, H.w, L.w);
    hi[i] = H;
    lo[i] = L;
}

__global__ void transpose_split_kernel(const float* __restrict__ x,
                                       __nv_bfloat16* __restrict__ hi,
                                       __nv_bfloat16* __restrict__ lo) {
    int idx = blockIdx.x * blockDim.x + threadIdx.x;
    if (idx >= MROWS * FEAD) return;
    int f = idx % FEAD;
    int m = idx / FEAD;
    int b = m % BSZ;
    int t = m / BSZ;
    float v = x[((size_t)b * TSZ + t) * FEAD + f];
    uint32_t uv = __float_as_uint(v);
    float hf = __uint_as_float(uv & 0xFFFF0000u);
    __nv_bfloat16 hb;
    *reinterpret_cast<uint16_t*>(&hb) = (uint16_t)(uv >> 16);
    hi[idx] = hb;
    lo[idx] = __float2bfloat16(v - hf);
}

// ---------------------------------------------------------------------------
// tf32 U-GEMM: U[800,3072] = h[800,1024] @ sru_W[1024,3072]
// UBM=160, UBN=128, UBK=32 — grid (24,5)=120 CTAs, zero M-padding.
// 320 threads = 10 warps (5 wrow x 2 wcol), 32x64 warp tile.
// ---------------------------------------------------------------------------
#define UK   1024
#define UN   3072
#define UBM  160
#define UBN  128
#define UBK  32
#define UNIT (UK / UBK)            // 32
#define UASTR 36                   // A row stride (floats): bank 4g+t, bijective
#define UBSTR 136                  // B row stride (floats): bank 8t+g, bijective
#define UA_PB (UBM * UASTR * 4)    // 23040 B
#define UB_PB (UBK * UBSTR * 4)    // 17408 B
#define U_SM_A 0
#define U_SM_B (2 * UA_PB)         // 46080
#define U_SM_TOTAL (U_SM_B + 2 * UB_PB)   // 80896

__global__ __launch_bounds__(320, 1)
void u_gemm_kernel(const float* __restrict__ A,
                   const float* __restrict__ Bf,
                   float* __restrict__ U) {
    extern __shared__ char dsm[];
    uint32_t smem;
    asm("{ .reg .u64 t; cvta.to.shared.u64 t, %1; cvt.u32.u64 %0, t; }"
        : "=r"(smem) : "l"(dsm));

    const int tid  = threadIdx.x;
    const int warp = tid >> 5;
    const int lane = tid & 31;
    const int wrow = warp >> 1;        // 0..4
    const int wcol = warp & 1;         // 0..1
    const int row0 = blockIdx.y * UBM;
    const int col0 = blockIdx.x * UBN;
    const int lg = lane >> 2;          // 0..7
    const int lt = lane & 3;           // 0..3

    float acc[2][8][4];
#pragma unroll
    for (int a = 0; a < 2; a++)
#pragma unroll
        for (int b = 0; b < 8; b++)
#pragma unroll
            for (int c = 0; c < 4; c++) acc[a][b][c] = 0.0f;

    auto stage = [&](int it, int buf) {
        const int k0 = it * UBK;
        // A: 160 rows x 8 float4-chunks = 1280; 4 per thread
#pragma unroll
        for (int i = 0; i < 4; i++) {
            int idx = tid + i * 320;
            int r = idx >> 3, kc = idx & 7;
            uint32_t daddr = smem + U_SM_A + buf * UA_PB + r * (UASTR * 4) + kc * 16;
            cpa16s(daddr, A + (size_t)(row0 + r) * UK + k0 + kc * 4);
        }
        // B: 32 rows x 32 float4-chunks = 1024; 3-4 per thread
#pragma unroll
        for (int i = 0; i < 4; i++) {
            int idx = tid + i * 320;
            if (idx < 1024) {
                int r = idx >> 5, f4 = idx & 31;
                uint32_t daddr = smem + U_SM_B + buf * UB_PB + r * (UBSTR * 4) + f4 * 16;
                cpa16s(daddr, Bf + (size_t)(k0 + r) * UN + col0 + f4 * 4);
            }
        }
    };

    stage(0, 0);
    cp_commit();

    for (int it = 0; it < UNIT; ++it) {
        if (it + 1 < UNIT) {
            stage(it + 1, (it + 1) & 1);
            cp_commit();
            cp_wait1();
        } else {
            cp_wait0();
        }
        __syncthreads();
        const int buf = it & 1;
        const float* fA = (const float*)(dsm + U_SM_A + buf * UA_PB);
        const float* fB = (const float*)(dsm + U_SM_B + buf * UB_PB);

#pragma unroll
        for (int kk = 0; kk < 4; kk++) {            // 4 x k8
            uint32_t af[2][4];
#pragma unroll
            for (int mt = 0; mt < 2; mt++) {
                int rb = wrow * 32 + mt * 16 + lg;
                int cb = kk * 8 + lt;
                af[mt][0] = f2tf(fA[rb * UASTR + cb]);
                af[mt][1] = f2tf(fA[(rb + 8) * UASTR + cb]);
                af[mt][2] = f2tf(fA[rb * UASTR + cb + 4]);
                af[mt][3] = f2tf(fA[(rb + 8) * UASTR + cb + 4]);
            }
            uint32_t bf2[8][2];
#pragma unroll
            for (int nt = 0; nt < 8; nt++) {
                int n = wcol * 64 + nt * 8 + lg;
                int k = kk * 8 + lt;
                bf2[nt][0] = f2tf(fB[k * UBSTR + n]);
                bf2[nt][1] = f2tf(fB[(k + 4) * UBSTR + n]);
            }
#pragma unroll
            for (int mt = 0; mt < 2; mt++)
#pragma unroll
                for (int nt = 0; nt < 8; nt++) {
                    float* d = acc[mt][nt];
                    mma_tf32(d[0], d[1], d[2], d[3], af[mt], bf2[nt]);
                }
        }
        __syncthreads();
    }

    // Epilogue (all rows valid: 5*160 = 800 exactly)
#pragma unroll
    for (int mt = 0; mt < 2; mt++) {
#pragma unroll
        for (int half = 0; half < 2; half++) {
            int row = row0 + wrow * 32 + mt * 16 + lg + half * 8;
            float* dst = U + (size_t)row * UN;
#pragma unroll
            for (int nt = 0; nt < 8; nt++) {
                int col = col0 + wcol * 64 + nt * 8 + lt * 2;
                float2 v;
                v.x = acc[mt][nt][half * 2 + 0];
                v.y = acc[mt][nt][half * 2 + 1];
                *reinterpret_cast<float2*>(dst + col) = v;
            }
        }
    }
}

// ---------------------------------------------------------------------------
// Dense GEMM (bf16x3, pre-split weights)
// ---------------------------------------------------------------------------
#define BM 64
#define BN 128
#define BK 16

template<int RELU, int REMAP, int WF32, int WSPLIT>
__global__ __launch_bounds__(256, 2)
void mma_gemm(const __nv_bfloat16* __restrict__ Ahi, const __nv_bfloat16* __restrict__ Alo,
              const __nv_bfloat16* __restrict__ Bhi, const __nv_bfloat16* __restrict__ Blo,
              const float* __restrict__ bias,
              float* __restrict__ Cf,
              __nv_bfloat16* __restrict__ Chi, __nv_bfloat16* __restrict__ Clo,
              int M, int K, int N) {
    __shared__ __nv_bfloat16 sAh[2][BM][24];
    __shared__ __nv_bfloat16 sAl[2][BM][24];
    __shared__ __nv_bfloat16 sBh[2][BK][136];
    __shared__ __nv_bfloat16 sBl[2][BK][136];

    const int tid  = threadIdx.x;
    const int lane = tid & 31;
    const int warp = tid >> 5;
    const int wm = warp >> 2;
    const int wn = warp & 3;
    const int row0 = blockIdx.y * BM;
    const int col0 = blockIdx.x * BN;
    const bool nAligned = ((N & 7) == 0);

    const int a_part = tid >> 7;
    const int a_m    = (tid & 127) >> 1;
    const int a_half = tid & 1;
    const int b_kr   = tid >> 4;
    const int b_ch   = tid & 15;

    float acc[2][4][4];
#pragma unroll
    for (int mt = 0; mt < 2; mt++)
#pragma unroll
        for (int nt = 0; nt < 4; nt++)
#pragma unroll
            for (int j = 0; j < 4; j++) acc[mt][nt][j] = 0.0f;

    const int NTILES = (K + BK - 1) / BK;

    auto stage = [&](int k0, int buf) {
        {
            const __nv_bfloat16* src = a_part ? Alo : Ahi;
            __nv_bfloat16* dst = a_part ? &sAl[buf][a_m][a_half * 8]
                                        : &sAh[buf][a_m][a_half * 8];
            int gr = row0 + a_m;
            int gk = k0 + a_half * 8;
            bool p = (gr < M) && (gk < K);
            cpa16(dst, src + (size_t)gr * K + gk, p);
        }
        {
            int gk = k0 + b_kr;
            int gn = col0 + b_ch * 8;
            if (nAligned) {
                bool p = (gk < K) && (gn < N);
                cpa16(&sBh[buf][b_kr][b_ch * 8], Bhi + (size_t)gk * N + gn, p);
                cpa16(&sBl[buf][b_kr][b_ch * 8], Blo + (size_t)gk * N + gn, p);
            } else {
#pragma unroll
                for (int j = 0; j < 8; j++) {
                    int c = gn + j;
                    bool p = (gk < K) && (c < N);
                    sBh[buf][b_kr][b_ch * 8 + j] = p ? Bhi[(size_t)gk * N + c] : __nv_bfloat16(0.0f);
                    sBl[buf][b_kr][b_ch * 8 + j] = p ? Blo[(size_t)gk * N + c] : __nv_bfloat16(0.0f);
                }
            }
        }
    };

    stage(0, 0);
    cp_commit();

    for (int it = 0; it < NTILES; ++it) {
        if (it + 1 < NTILES) stage((it + 1) * BK, (it + 1) & 1);
        cp_commit();
        cp_wait1();
        __syncthreads();

        const int buf = it & 1;
        uint32_t ah[2][4], al[2][4], bh[4][2], bl[4][2];
#pragma unroll
        for (int mt = 0; mt < 2; mt++) {
            int r = wm * 32 + mt * 16 + (lane & 15);
            int kk = (lane >> 4) * 8;
            ldsm_x4_p(ah[mt], &sAh[buf][r][kk]);
            ldsm_x4_p(al[mt], &sAl[buf][r][kk]);
        }
#pragma unroll
        for (int nt = 0; nt < 4; nt++) {
            int n0 = wn * 32 + nt * 8;
            int kr = lane & 15;
            ldsm_x2_t(bh[nt], &sBh[buf][kr][n0]);
            ldsm_x2_t(bl[nt], &sBl[buf][kr][n0]);
        }
#pragma unroll
        for (int mt = 0; mt < 2; mt++) {
#pragma unroll
            for (int nt = 0; nt < 4; nt++) {
                float* d = acc[mt][nt];
                mma_bf16(d[0], d[1], d[2], d[3], ah[mt], bh[nt]);
                mma_bf16(d[0], d[1], d[2], d[3], ah[mt], bl[nt]);
                mma_bf16(d[0], d[1], d[2], d[3], al[mt], bh[nt]);
            }
        }
        __syncthreads();
    }

#pragma unroll
    for (int mt = 0; mt < 2; mt++) {
#pragma unroll
        for (int nt = 0; nt < 4; nt++) {
            int rbase = row0 + wm * 32 + mt * 16 + (lane >> 2);
            int cbase = col0 + wn * 32 + nt * 8 + ((lane & 3) << 1);
#pragma unroll
            for (int half = 0; half < 2; half++) {
                int row = rbase + half * 8;
                if (row >= M) continue;
                int orow = row;
                if (REMAP) {
                    int bb = row % BSZ;
                    int tt = row / BSZ;
                    orow = bb * TSZ + tt;
                }
#pragma unroll
                for (int j = 0; j < 2; j++) {
                    int col = cbase + j;
                    if (col >= N) continue;
                    float v = acc[mt][nt][half * 2 + j];
                    if (bias) v += bias[col];
                    if (RELU) v = fmaxf(v, 0.0f);
                    size_t o = (size_t)orow * N + col;
                    if (WF32) Cf[o] = v;
                    if (WSPLIT) {
                        uint32_t uv = __float_as_uint(v);
                        float hf = __uint_as_float(uv & 0xFFFF0000u);
                        *reinterpret_cast<uint16_t*>(&Chi[o]) = (uint16_t)(uv >> 16);
                        Clo[o] = __float2bfloat16(v - hf);
                    }
                }
            }
        }
    }
}

// ---------------------------------------------------------------------------
// SRU recurrence. WSPLIT=1 only for the last layer (feeds W3's bf16 input).
// ---------------------------------------------------------------------------
template<int WSPLIT>
__global__ __launch_bounds__(128)
void sru_scan_kernel(const float* __restrict__ U, const float* __restrict__ c0,
                     const float* __restrict__ sb, float* __restrict__ h,
                     __nv_bfloat16* __restrict__ Ahi, __nv_bfloat16* __restrict__ Alo,
                     float* __restrict__ c_out) {
    int idx = blockIdx.x * 128 + threadIdx.x;
    if (idx >= BSZ * HDIM) return;
    int hh = idx & (HDIM - 1);
    int b  = idx >> 10;
    float c  = c0[idx];
    float bf = sb[hh];
    float br = sb[HDIM + hh];
#pragma unroll
    for (int t0 = 0; t0 < TSZ; t0 += 5) {
        float xf[5], uf[5], ur[5], hv[5];
#pragma unroll
        for (int i = 0; i < 5; i++) {
            int row = (t0 + i) * BSZ + b;
            const float* Ur = U + (size_t)row * (3 * HDIM);
            xf[i] = Ur[hh];
            uf[i] = Ur[HDIM + hh];
            ur[i] = Ur[2 * HDIM + hh];
            hv[i] = h[(size_t)row * HDIM + hh];
        }
#pragma unroll
        for (int i = 0; i < 5; i++) {
            float f = sigmoid_fast(uf[i] + bf);
            float r = sigmoid_fast(ur[i] + br);
            c = f * c + (1.0f - f) * xf[i];
            float hn = r * tanh_fast(c) + (1.0f - r) * hv[i];
            size_t o = (size_t)((t0 + i) * BSZ + b) * HDIM + hh;
            h[o] = hn;
            if (WSPLIT) {
                uint32_t uv = __float_as_uint(hn);
                float hf = __uint_as_float(uv & 0xFFFF0000u);
                *reinterpret_cast<uint16_t*>(&Ahi[o]) = (uint16_t)(uv >> 16);
                Alo[o] = __float2bfloat16(hn - hf);
            }
        }
    }
    c_out[idx] = c;
}

// ---------------------------------------------------------------------------
extern "C" void kernel_launch(void* const* d_in, const int* in_sizes, int n_in,
                              void* d_out, int out_size) {
    const float* x      = (const float*)d_in[0];
    const float* hidden = (const float*)d_in[1];
    const float* W1     = (const float*)d_in[2];
    const float* b1     = (const float*)d_in[3];
    const float* sru_W  = (const float*)d_in[4];
    const float* sru_b  = (const float*)d_in[5];
    const float* W3     = (const float*)d_in[6];
    const float* b3     = (const float*)d_in[7];
    const float* W4     = (const float*)d_in[8];
    const float* b4     = (const float*)d_in[9];
    float* out = (float*)d_out;

    float *h, *U;
    __nv_bfloat16 *xthi, *xtlo, *Ahi, *Alo, *A2hi, *A2lo, *Wsmhi, *Wsmlo;
    cudaGetSymbolAddress((void**)&h,    g_h);
    cudaGetSymbolAddress((void**)&U,    g_U);
    cudaGetSymbolAddress((void**)&xthi, g_xthi);
    cudaGetSymbolAddress((void**)&xtlo, g_xtlo);
    cudaGetSymbolAddress((void**)&Ahi,  g_Ahi);
    cudaGetSymbolAddress((void**)&Alo,  g_Alo);
    cudaGetSymbolAddress((void**)&A2hi, g_A2hi);
    cudaGetSymbolAddress((void**)&A2lo, g_A2lo);
    cudaGetSymbolAddress((void**)&Wsmhi, g_Wsmhi);
    cudaGetSymbolAddress((void**)&Wsmlo, g_Wsmlo);

    static bool attr_set = false;
    if (!attr_set) {
        cudaFuncSetAttribute(u_gemm_kernel,
                             cudaFuncAttributeMaxDynamicSharedMemorySize, U_SM_TOTAL);
        attr_set = true;
    }

    // Preprocessing: small-weight splits + input transpose
    transpose_split_kernel<<<(MROWS * FEAD + 255) / 256, 256>>>(x, xthi, xtlo);
    split8_kernel<<<(N_W1 / 8 + 255) / 256, 256>>>((const float4*)W1, (uint4*)(Wsmhi + OFF_W1), (uint4*)(Wsmlo + OFF_W1), N_W1 / 8);
    split8_kernel<<<(N_W3 / 8 + 255) / 256, 256>>>((const float4*)W3, (uint4*)(Wsmhi + OFF_W3), (uint4*)(Wsmlo + OFF_W3), N_W3 / 8);
    split8_kernel<<<(N_W4 / 8 + 255) / 256, 256>>>((const float4*)W4, (uint4*)(Wsmhi + OFF_W4), (uint4*)(Wsmlo + OFF_W4), N_W4 / 8);

    const int GY = (MROWS + BM - 1) / BM;

    // Dense layer 1: h = xt @ W1 + b1 (fp32 out; U-GEMM consumes fp32 directly)
    {
        dim3 grid((HDIM + BN - 1) / BN, GY);
        mma_gemm<0, 0, 1, 0><<<grid, 256>>>(xthi, xtlo, Wsmhi + OFF_W1, Wsmlo + OFF_W1,
                                            b1, h, nullptr, nullptr, MROWS, FEAD, HDIM);
    }

    // SRU layers: tf32 U-GEMM (raw fp32 operands) + scan
    for (int l = 0; l < LNUM; l++) {
        dim3 gridU(UN / UBN, MROWS / UBM);   // 24 x 5 = 120 CTAs
        u_gemm_kernel<<<gridU, 320, U_SM_TOTAL>>>(h, sru_W + (size_t)l * HDIM * 3 * HDIM, U);
        if (l < LNUM - 1) {
            sru_scan_kernel<0><<<(BSZ * HDIM + 127) / 128, 128>>>(
                U, hidden + (size_t)l * BSZ * HDIM, sru_b + (size_t)l * 2 * HDIM,
                h, nullptr, nullptr, out + OUT_ELEMS + (size_t)l * BSZ * HDIM);
        } else {
            sru_scan_kernel<1><<<(BSZ * HDIM + 127) / 128, 128>>>(
                U, hidden + (size_t)l * BSZ * HDIM, sru_b + (size_t)l * 2 * HDIM,
                h, Ahi, Alo, out + OUT_ELEMS + (size_t)l * BSZ * HDIM);
        }
    }

    // Dense ReLU with row remap (input: last scan's bf16 split)
    {
        dim3 grid((HDIM + BN - 1) / BN, GY);
        mma_gemm<1, 1, 0, 1><<<grid, 256>>>(Ahi, Alo, Wsmhi + OFF_W3, Wsmlo + OFF_W3,
                                            b3, nullptr, A2hi, A2lo, MROWS, HDIM, HDIM);
    }

    // Output projection
    {
        dim3 grid((OUTD + BN - 1) / BN, GY);
        mma_gemm<0, 0, 1, 0><<<grid, 256>>>(A2hi, A2lo, Wsmhi + OFF_W4, Wsmlo + OFF_W4,
                                            b4, out, nullptr, nullptr, MROWS, HDIM, OUTD);
    }
}